// round 12
// baseline (speedup 1.0000x reference)
#include <cuda_runtime.h>
#include <cuda_bf16.h>
#include <mma.h>
#include <math.h>
#include <stdint.h>

using namespace nvcuda;

#define BATCH 4
#define NPTS  4096
#define KNN   20
#define FINF  __int_as_float(0x7f800000)
#define FULLM 0xffffffffu
#define U64MAX 0xffffffffffffffffull

typedef unsigned long long u64;

// ---------------- scratch (device globals; no allocations allowed) ----------
__device__ float g_dmat[BATCH * NPTS * NPTS];    // -sim for cosine knn (268MB)
__device__ int   g_idx [BATCH * NPTS * KNN];
__device__ float g_xc  [BATCH * 192 * NPTS];     // concat x1|x2|x3
__device__ float g_uv  [BATCH * 128 * NPTS];     // U rows 0-63, V rows 64-127 (ch-major)
__device__ float g_uvt [BATCH * NPTS * 128];     // point-major copy: uvt[n][c]
__device__ float g_w2  [128 * 64];               // [w0a ; w0b-w0a]
__device__ __nv_bfloat16 g_hx[BATCH * 64 * NPTS];  // hi plane, k-major [c][n]
__device__ __nv_bfloat16 g_lx[BATCH * 64 * NPTS];  // lo plane, k-major [c][n]
__device__ float g_gpart[BATCH * 1024 * 64];
__device__ float g_g   [BATCH * 1024];
__device__ float g_gterm[BATCH * 512];
__device__ float g_h1  [BATCH * 512 * NPTS];
__device__ float g_h2  [BATCH * 256 * NPTS];

__device__ __forceinline__ float lrelu(float v) { return v >= 0.f ? v : 0.2f * v; }

__device__ __forceinline__ u64 splat2(float a) {
    u64 r;
    unsigned int ai = __float_as_uint(a);
    asm("mov.b64 %0, {%1, %1};" : "=l"(r) : "r"(ai));
    return r;
}
__device__ __forceinline__ void fma2(u64& d, u64 a, u64 b) {
    asm("fma.rn.f32x2 %0, %1, %2, %0;" : "+l"(d) : "l"(a), "l"(b));
}
__device__ __forceinline__ void unpack2(u64 v, float& lo, float& hi) {
    unsigned int l, h;
    asm("mov.b64 {%0, %1}, %2;" : "=r"(l), "=r"(h) : "l"(v));
    lo = __uint_as_float(l); hi = __uint_as_float(h);
}

// ---------------- u64 key top-k machinery ----------------
__device__ __forceinline__ u64 fkey(float d, int j) {
    unsigned int u = __float_as_uint(d);
    u = (u & 0x80000000u) ? ~u : (u | 0x80000000u);
    return ((u64)u << 32) | (unsigned int)j;
}

#define INS5(key) do {                                              \
    u64 _k = (key);                                                 \
    if (_k < c4) {                                                  \
        if (_k < c3) { c4 = c3;                                     \
            if (_k < c2) { c3 = c2;                                 \
                if (_k < c1) { c2 = c1;                             \
                    if (_k < c0) { c1 = c0; c0 = _k; } else c1 = _k;\
                } else c2 = _k;                                     \
            } else c3 = _k;                                         \
        } else c4 = _k;                                             \
    }                                                               \
} while (0)

__device__ __forceinline__ u64 warp_min_u64(u64 v) {
#pragma unroll
    for (int off = 16; off > 0; off >>= 1) {
        u64 o = __shfl_xor_sync(FULLM, v, off);
        v = (o < v) ? o : v;
    }
    return v;
}

__device__ __forceinline__ u64 tk5_merge(u64& c0, u64& c1, u64& c2, u64& c3, u64& c4,
                                         int lane, int* outrow, bool& need2) {
    int pops = 0;
    u64 w = 0;
#pragma unroll 1
    for (int r = 0; r < KNN; r++) {
        w = warp_min_u64(c0);
        if (c0 == w) { c0 = c1; c1 = c2; c2 = c3; c3 = c4; c4 = U64MAX; pops++; }
        if (lane == 0) outrow[r] = (int)(w & 0xffffffffu);
    }
    need2 = __any_sync(FULLM, pops >= 5);
    return w;
}

__device__ __forceinline__ void tk_select_buf(const u64* buf, int m, int lane, int* outrow) {
    u64 k0 = (lane < m) ? buf[lane] : U64MAX;
    u64 k1 = (32 + lane < m) ? buf[32 + lane] : U64MAX;
#pragma unroll 1
    for (int r = 0; r < KNN; r++) {
        u64 lm = (k0 < k1) ? k0 : k1;
        u64 w = warp_min_u64(lm);
        if (k0 == w) k0 = U64MAX;
        else if (k1 == w) k1 = U64MAX;
        if (lane == 0) outrow[r] = (int)(w & 0xffffffffu);
    }
}

// ---------------- kNN euclid (C=6, warp per query) ----------------
__global__ __launch_bounds__(256)
void k_knn_euclid(const float* __restrict__ x) {
    __shared__ u64 sbuf[8][64];
    int b = blockIdx.y;
    int warp = threadIdx.x >> 5, lane = threadIdx.x & 31;
    int i = blockIdx.x * 8 + warp;
    const float* xb = x + b * 6 * NPTS;
    float xi[6];
#pragma unroll
    for (int c = 0; c < 6; c++) xi[c] = xb[c * NPTS + i];
    float sqi = 0.f;
#pragma unroll
    for (int c = 0; c < 6; c++) sqi = fmaf(xi[c], xi[c], sqi);

    u64 c0 = U64MAX, c1 = U64MAX, c2 = U64MAX, c3 = U64MAX, c4 = U64MAX;
    for (int tblk = 0; tblk < NPTS; tblk += 128) {
        int j0 = tblk + lane * 4;
        float4 row[6];
#pragma unroll
        for (int c = 0; c < 6; c++) row[c] = *(const float4*)&xb[c * NPTS + j0];
        float d0 = sqi, d1 = sqi, d2 = sqi, d3 = sqi;
#pragma unroll
        for (int c = 0; c < 6; c++) {
            d0 = fmaf(row[c].x - 2.f * xi[c], row[c].x, d0);
            d1 = fmaf(row[c].y - 2.f * xi[c], row[c].y, d1);
            d2 = fmaf(row[c].z - 2.f * xi[c], row[c].z, d2);
            d3 = fmaf(row[c].w - 2.f * xi[c], row[c].w, d3);
        }
        INS5(fkey(d0, j0));
        INS5(fkey(d1, j0 + 1));
        INS5(fkey(d2, j0 + 2));
        INS5(fkey(d3, j0 + 3));
    }
    int* outrow = g_idx + (b * NPTS + i) * KNN;
    bool need2;
    u64 Tp = tk5_merge(c0, c1, c2, c3, c4, lane, outrow, need2);

    if (need2) {
        u64* buf = sbuf[warp];
        int base = 0;
        for (int tblk = 0; tblk < NPTS; tblk += 128) {
            int j0 = tblk + lane * 4;
            float4 row[6];
#pragma unroll
            for (int c = 0; c < 6; c++) row[c] = *(const float4*)&xb[c * NPTS + j0];
            float dd[4] = {sqi, sqi, sqi, sqi};
#pragma unroll
            for (int c = 0; c < 6; c++) {
                dd[0] = fmaf(row[c].x - 2.f * xi[c], row[c].x, dd[0]);
                dd[1] = fmaf(row[c].y - 2.f * xi[c], row[c].y, dd[1]);
                dd[2] = fmaf(row[c].z - 2.f * xi[c], row[c].z, dd[2]);
                dd[3] = fmaf(row[c].w - 2.f * xi[c], row[c].w, dd[3]);
            }
#pragma unroll
            for (int q = 0; q < 4; q++) {
                u64 k = fkey(dd[q], j0 + q);
                bool p = (k <= Tp);
                unsigned m = __ballot_sync(FULLM, p);
                int pos = base + __popc(m & ((1u << lane) - 1u));
                if (p && pos < 64) buf[pos] = k;
                base += __popc(m);
            }
        }
        __syncwarp();
        tk_select_buf(buf, base < 64 ? base : 64, lane, outrow);
    }
}

// ---------------- top-k from materialized (-sim) matrix (warp per row) ------
__global__ __launch_bounds__(256)
void k_topk_dmat() {
    __shared__ u64 sbuf[8][64];
    int b = blockIdx.y;
    int warp = threadIdx.x >> 5, lane = threadIdx.x & 31;
    int i = blockIdx.x * 8 + warp;
    const float* row = g_dmat + ((long)(b * NPTS + i)) * NPTS;

    u64 c0 = U64MAX, c1 = U64MAX, c2 = U64MAX, c3 = U64MAX, c4 = U64MAX;
    for (int tblk = 0; tblk < NPTS; tblk += 128) {
        int j0 = tblk + lane * 4;
        float4 v = *(const float4*)&row[j0];
        INS5(fkey(v.x, j0));
        INS5(fkey(v.y, j0 + 1));
        INS5(fkey(v.z, j0 + 2));
        INS5(fkey(v.w, j0 + 3));
    }
    int* outrow = g_idx + (b * NPTS + i) * KNN;
    bool need2;
    u64 Tp = tk5_merge(c0, c1, c2, c3, c4, lane, outrow, need2);

    if (need2) {
        u64* buf = sbuf[warp];
        int base = 0;
        for (int tblk = 0; tblk < NPTS; tblk += 128) {
            int j0 = tblk + lane * 4;
            float4 v = *(const float4*)&row[j0];
            u64 kk[4] = {fkey(v.x, j0), fkey(v.y, j0 + 1), fkey(v.z, j0 + 2), fkey(v.w, j0 + 3)};
#pragma unroll
            for (int q = 0; q < 4; q++) {
                bool p = (kk[q] <= Tp);
                unsigned m = __ballot_sync(FULLM, p);
                int pos = base + __popc(m & ((1u << lane) - 1u));
                if (p && pos < 64) buf[pos] = kk[q];
                base += __popc(m);
            }
        }
        __syncwarp();
        tk_select_buf(buf, base < 64 ? base : 64, lane, outrow);
    }
}

// ---------------- normalize + bf16 hi/lo split into k-major planes ----------
__global__ void k_xsplit(int srcrow) {
    int b = blockIdx.y;
    int n = blockIdx.x * 256 + threadIdx.x;
    const float* src = g_xc + ((long)b * 192 + srcrow) * NPTS;
    float v[64]; float s = 0.f;
#pragma unroll
    for (int c = 0; c < 64; c++) { v[c] = src[c * NPTS + n]; s = fmaf(v[c], v[c], s); }
    float inv = 1.f / (sqrtf(s) + 1e-8f);
    __nv_bfloat16* H = g_hx + (long)b * 64 * NPTS;
    __nv_bfloat16* L = g_lx + (long)b * 64 * NPTS;
#pragma unroll
    for (int c = 0; c < 64; c++) {
        float xv = v[c] * inv;
        __nv_bfloat16 h = __float2bfloat16(xv);
        __nv_bfloat16 l = __float2bfloat16(xv - __bfloat162float(h));
        H[c * NPTS + n] = h;    // coalesced over n
        L[c * NPTS + n] = l;
    }
}

// ---------------- WMMA sim GEMM: dmat[m][n] = -(HH + HL + LH)[m][n] --------
// Zero smem, zero syncs: fragments load straight from k-major planes in L2.
// 128x128 tile/block, 8 warps (4m x 2n), warp tile 32x64.
__global__ __launch_bounds__(256)
void k_sim_wmma() {
    int b = blockIdx.z, m0 = blockIdx.y * 128, n0 = blockIdx.x * 128;
    int wid = threadIdx.x >> 5;
    int wm = wid & 3, wn = wid >> 2;

    wmma::fragment<wmma::accumulator, 16, 16, 16, float> c[2][4];
#pragma unroll
    for (int i = 0; i < 2; i++)
#pragma unroll
        for (int j = 0; j < 4; j++) wmma::fill_fragment(c[i][j], 0.f);

    const __nv_bfloat16* H = g_hx + (long)b * 64 * NPTS;
    const __nv_bfloat16* L = g_lx + (long)b * 64 * NPTS;
    const __nv_bfloat16* Aplane[3] = {H, H, L};
    const __nv_bfloat16* Bplane[3] = {H, L, H};

#pragma unroll 1
    for (int g = 0; g < 3; g++) {
        const __nv_bfloat16* Ap = Aplane[g];
        const __nv_bfloat16* Bp = Bplane[g];
#pragma unroll
        for (int ks = 0; ks < 4; ks++) {
            long ko = (long)(ks * 16) * NPTS;
            wmma::fragment<wmma::matrix_a, 16, 16, 16, __nv_bfloat16, wmma::col_major> af[2];
            wmma::fragment<wmma::matrix_b, 16, 16, 16, __nv_bfloat16, wmma::row_major> bf[4];
#pragma unroll
            for (int i = 0; i < 2; i++)
                wmma::load_matrix_sync(af[i], Ap + ko + (m0 + wm * 32 + i * 16), NPTS);
#pragma unroll
            for (int j = 0; j < 4; j++)
                wmma::load_matrix_sync(bf[j], Bp + ko + (n0 + wn * 64 + j * 16), NPTS);
#pragma unroll
            for (int i = 0; i < 2; i++)
#pragma unroll
                for (int j = 0; j < 4; j++)
                    wmma::mma_sync(c[i][j], af[i], bf[j], c[i][j]);
        }
    }

    float* dmb = g_dmat + (long)b * NPTS * NPTS;
#pragma unroll
    for (int i = 0; i < 2; i++)
#pragma unroll
        for (int j = 0; j < 4; j++) {
            for (int e = 0; e < c[i][j].num_elements; e++) c[i][j].x[e] = -c[i][j].x[e];
            wmma::store_matrix_sync(
                &dmb[(long)(m0 + wm * 32 + i * 16) * NPTS + n0 + wn * 64 + j * 16],
                c[i][j], NPTS, wmma::mem_row_major);
        }
}

// ---------------- build W2 = [w0a ; w0b - w0a] ----------------
__global__ void k_w2prep(const float* __restrict__ w0, int C) {
    int e = blockIdx.x * 256 + threadIdx.x;
    if (e >= 128 * C) return;
    int o = e / C, c = e % C;
    float val = (o < 64) ? w0[o * (2 * C) + c]
                         : (w0[(o - 64) * (2 * C) + C + c] - w0[(o - 64) * (2 * C) + c]);
    g_w2[o * C + c] = val;
}

// ---------------- transpose g_uv (ch-major) -> g_uvt (point-major) ----------
__global__ void k_uvt() {
    __shared__ float t[32][33];
    int b = blockIdx.z;
    int cb = blockIdx.x * 32, nb = blockIdx.y * 32;
    int tx = threadIdx.x & 31, ty = threadIdx.x >> 5;  // ty 0..7
    const float* src = g_uv + (long)b * 128 * NPTS;
    float* dst = g_uvt + (long)b * NPTS * 128;
#pragma unroll
    for (int k = 0; k < 4; k++)
        t[ty + 8 * k][tx] = src[(long)(cb + ty + 8 * k) * NPTS + nb + tx];
    __syncthreads();
#pragma unroll
    for (int k = 0; k < 4; k++)
        dst[(long)(nb + ty + 8 * k) * 128 + cb + tx] = t[tx][ty + 8 * k];
}

// ---------------- post-op ----------------
__device__ __forceinline__ float gemm_post(float v, int gm, int b, int M,
                                           const float* addrow, const float* s,
                                           const float* o, int act, int negate) {
    if (addrow) v += addrow[b * M + gm];
    if (s) v *= s[gm];
    if (o) v += o[gm];
    if (act) v = lrelu(v);
    if (negate) v = -v;
    return v;
}

// ---------------- big GEMM: 128x128 tile, 8x8/thread, fma.f32x2 -------------
__global__ __launch_bounds__(256, 2)
void k_gemm_big(const float* __restrict__ A, long a_bs, int as_m, long as_k, int a_colmajor,
                const float* __restrict__ X, long x_bs,
                float* __restrict__ Y, long y_bs,
                int M, int K,
                const float* __restrict__ addrow,
                const float* __restrict__ s, const float* __restrict__ o,
                int act, int negate,
                float* __restrict__ ypart) {
    __shared__ float As[16][128];
    __shared__ float Xs[16][128];
    int b = blockIdx.z;
    int m0 = blockIdx.y * 128, n0 = blockIdx.x * 128;
    const float* Ab = A + (long)b * a_bs;
    const float* Xb = X + (long)b * x_bs;
    int tid = threadIdx.x;
    int ty = tid >> 4, tx = tid & 15;

    u64 acc[8][4];
#pragma unroll
    for (int i = 0; i < 8; i++)
#pragma unroll
        for (int j = 0; j < 4; j++) acc[i][j] = 0ull;

    for (int k0 = 0; k0 < K; k0 += 16) {
        if (a_colmajor) {
            for (int e = tid; e < 512; e += 256) {
                int kk = e >> 5, m4 = e & 31;
                *(float4*)&As[kk][m4 * 4] =
                    *(const float4*)&Ab[(long)(k0 + kk) * as_k + (m0 + m4 * 4)];
            }
        } else {
            for (int e = tid; e < 2048; e += 256) {
                int mm = e >> 4, kk = e & 15;
                int gm = m0 + mm;
                As[kk][mm] = (gm < M) ? Ab[(long)gm * as_m + (k0 + kk)] : 0.f;
            }
        }
        for (int e = tid; e < 512; e += 256) {
            int kk = e >> 5, n4 = e & 31;
            *(float4*)&Xs[kk][n4 * 4] =
                *(const float4*)&Xb[(long)(k0 + kk) * NPTS + n0 + n4 * 4];
        }
        __syncthreads();
#pragma unroll
        for (int kk = 0; kk < 16; kk++) {
            float a[8];
            *(float4*)a       = *(float4*)&As[kk][ty * 8];
            *(float4*)(a + 4) = *(float4*)&As[kk][ty * 8 + 4];
            u64 xv[4];
#pragma unroll
            for (int j = 0; j < 4; j++) xv[j] = *(u64*)&Xs[kk][tx * 8 + j * 2];
#pragma unroll
            for (int i = 0; i < 8; i++) {
                u64 ai = splat2(a[i]);
#pragma unroll
                for (int j = 0; j < 4; j++) fma2(acc[i][j], ai, xv[j]);
            }
        }
        __syncthreads();
    }

    if (ypart) {  // fused global max-pool across this N-tile
        float* red = &As[0][0];
#pragma unroll
        for (int i = 0; i < 8; i++) {
            int gm = m0 + ty * 8 + i;
            int gmc = gm < M ? gm : 0;
            float mloc = -FINF;
#pragma unroll
            for (int j = 0; j < 4; j++) {
                float lo, hi;
                unpack2(acc[i][j], lo, hi);
                lo = gemm_post(lo, gmc, b, M, addrow, s, o, act, negate);
                hi = gemm_post(hi, gmc, b, M, addrow, s, o, act, negate);
                mloc = fmaxf(mloc, fmaxf(lo, hi));
            }
            red[(ty * 8 + i) * 16 + tx] = mloc;
        }
        __syncthreads();
        if (tid < 128) {
            float m = -FINF;
            for (int q = 0; q < 16; q++) m = fmaxf(m, red[tid * 16 + q]);
            int gm = m0 + tid;
            if (gm < M) ypart[((long)(b * M + gm)) * gridDim.x + blockIdx.x] = m;
        }
    } else {
#pragma unroll
        for (int i = 0; i < 8; i++) {
            int gm = m0 + ty * 8 + i;
            if (gm >= M) continue;
            float out8[8];
#pragma unroll
            for (int j = 0; j < 4; j++) {
                float lo, hi;
                unpack2(acc[i][j], lo, hi);
                out8[j * 2]     = gemm_post(lo, gm, b, M, addrow, s, o, act, negate);
                out8[j * 2 + 1] = gemm_post(hi, gm, b, M, addrow, s, o, act, negate);
            }
            float* dst = Y + (long)b * y_bs + (long)gm * NPTS + n0 + tx * 8;
            *(float4*)dst       = *(float4*)out8;
            *(float4*)(dst + 4) = *(float4*)(out8 + 4);
        }
    }
}

// ---------------- small-case GEMM (K=6 or M=13): 64x64 tile ----------------
#define BM 64
#define BN 64
#define BK 16

__global__ void k_gemm(const float* __restrict__ A, long a_bs, int as_m, long as_k, int a_colmajor,
                       const float* __restrict__ X, long x_bs,
                       float* __restrict__ Y, long y_bs,
                       int M, int K,
                       const float* __restrict__ addrow,
                       const float* __restrict__ s, const float* __restrict__ o,
                       int act, int negate) {
    __shared__ float As[BK][BM + 4];
    __shared__ float Xs[BK][BN + 4];
    int b = blockIdx.z;
    int m0 = blockIdx.y * BM, n0 = blockIdx.x * BN;
    const float* Ab = A + (long)b * a_bs;
    const float* Xb = X + (long)b * x_bs;
    int tid = threadIdx.x;
    int ty = tid >> 4, tx = tid & 15;
    float acc[4][4] = {};
    for (int k0 = 0; k0 < K; k0 += BK) {
        for (int e = tid; e < BK * BM; e += 256) {
            int mm = e >> 4, kk = e & 15;
            int gm = m0 + mm, gk = k0 + kk;
            As[kk][mm] = (gk < K && gm < M) ? Ab[(long)gm * as_m + (long)gk * as_k] : 0.f;
        }
        for (int e = tid; e < BK * BN; e += 256) {
            int kk = e >> 6, nn = e & 63;
            int gk = k0 + kk;
            Xs[kk][nn] = (gk < K) ? Xb[(long)gk * NPTS + n0 + nn] : 0.f;
        }
        __syncthreads();
#pragma unroll
        for (int kk = 0; kk < BK; kk++) {
            float a[4], xv[4];
#pragma unroll
            for (int i = 0; i < 4; i++) a[i] = As[kk][ty * 4 + i];
#pragma unroll
            for (int j = 0; j < 4; j++) xv[j] = Xs[kk][tx * 4 + j];
#pragma unroll
            for (int i = 0; i < 4; i++)
#pragma unroll
                for (int j = 0; j < 4; j++)
                    acc[i][j] = fmaf(a[i], xv[j], acc[i][j]);
        }
        __syncthreads();
    }
#pragma unroll
    for (int i = 0; i < 4; i++) {
        int gm = m0 + ty * 4 + i;
        if (gm >= M) continue;
#pragma unroll
        for (int j = 0; j < 4; j++) {
            float v = gemm_post(acc[i][j], gm, b, M, addrow, s, o, act, negate);
            Y[(long)b * y_bs + (long)gm * NPTS + n0 + tx * 4 + j] = v;
        }
    }
}

// ---------------- edge-conv 2nd half: gather (point-major) + GEMM + max ----
#define H0S 164   // padded col stride (160 cols)

__global__ void k_edge2(const float* __restrict__ w1,
                        const float* __restrict__ s0, const float* __restrict__ o0,
                        const float* __restrict__ s1, const float* __restrict__ o1,
                        int outrow) {
    extern __shared__ float sm[];
    float* w1s = sm;                  // 64*64   [o][c]
    float* h0s = w1s + 4096;          // 64*H0S  [c][col] -> overwritten by H1 [o][col]
    float* vcs = h0s + 64 * H0S;      // 8*64    [p][c] center V values
    float* s0s = vcs + 512;
    float* o0s = s0s + 64;
    float* s1s = o0s + 64;
    float* o1s = s1s + 64;
    int*   idxs = (int*)(o1s + 64);   // 160

    int tid = threadIdx.x;
    int b = blockIdx.y;
    int n0 = blockIdx.x * 8;
    const float* uvt = g_uvt + (long)b * NPTS * 128;

    for (int e = tid; e < 4096; e += 256) w1s[e] = w1[e];
    if (tid < 64) { s0s[tid] = s0[tid]; o0s[tid] = o0[tid]; s1s[tid] = s1[tid]; o1s[tid] = o1[tid]; }
    for (int e = tid; e < 160; e += 256)
        idxs[e] = g_idx[(b * NPTS + n0 + e / 20) * KNN + e % 20];
    if (tid < 128) {
        int p = tid >> 4, cq = tid & 15;
        *(((float4*)vcs) + tid) = *(const float4*)&uvt[(long)(n0 + p) * 128 + 64 + cq * 4];
    }
    __syncthreads();

    for (int e = tid; e < 16 * 160; e += 256) {
        int cq = e / 160, col = e - cq * 160;
        int p = col / 20;
        int j = idxs[col];
        float4 u = *(const float4*)&uvt[(long)j * 128 + cq * 4];
        float4 vv = *(((const float4*)vcs) + p * 16 + cq);
        int c = cq * 4;
        h0s[(c + 0) * H0S + col] = lrelu(fmaf(u.x + vv.x, s0s[c + 0], o0s[c + 0]));
        h0s[(c + 1) * H0S + col] = lrelu(fmaf(u.y + vv.y, s0s[c + 1], o0s[c + 1]));
        h0s[(c + 2) * H0S + col] = lrelu(fmaf(u.z + vv.z, s0s[c + 2], o0s[c + 2]));
        h0s[(c + 3) * H0S + col] = lrelu(fmaf(u.w + vv.w, s0s[c + 3], o0s[c + 3]));
    }
    __syncthreads();

    int ty = tid >> 4, tx = tid & 15;
    for (int iter = 0; iter < 3; iter++) {
        int g = tx + iter * 16;
        float acc[4][4] = {};
        if (g < 40) {
#pragma unroll
            for (int c4 = 0; c4 < 16; c4++) {
                float4 h[4], w[4];
#pragma unroll
                for (int q = 0; q < 4; q++) h[q] = *(const float4*)&h0s[(c4 * 4 + q) * H0S + g * 4];
#pragma unroll
                for (int q = 0; q < 4; q++) w[q] = *(const float4*)&w1s[(ty * 4 + q) * 64 + c4 * 4];
#pragma unroll
                for (int i = 0; i < 4; i++) {
                    acc[i][0] = fmaf(w[i].x, h[0].x, acc[i][0]);
                    acc[i][0] = fmaf(w[i].y, h[1].x, acc[i][0]);
                    acc[i][0] = fmaf(w[i].z, h[2].x, acc[i][0]);
                    acc[i][0] = fmaf(w[i].w, h[3].x, acc[i][0]);
                    acc[i][1] = fmaf(w[i].x, h[0].y, acc[i][1]);
                    acc[i][1] = fmaf(w[i].y, h[1].y, acc[i][1]);
                    acc[i][1] = fmaf(w[i].z, h[2].y, acc[i][1]);
                    acc[i][1] = fmaf(w[i].w, h[3].y, acc[i][1]);
                    acc[i][2] = fmaf(w[i].x, h[0].z, acc[i][2]);
                    acc[i][2] = fmaf(w[i].y, h[1].z, acc[i][2]);
                    acc[i][2] = fmaf(w[i].z, h[2].z, acc[i][2]);
                    acc[i][2] = fmaf(w[i].w, h[3].z, acc[i][2]);
                    acc[i][3] = fmaf(w[i].x, h[0].w, acc[i][3]);
                    acc[i][3] = fmaf(w[i].y, h[1].w, acc[i][3]);
                    acc[i][3] = fmaf(w[i].z, h[2].w, acc[i][3]);
                    acc[i][3] = fmaf(w[i].w, h[3].w, acc[i][3]);
                }
            }
        }
        __syncthreads();
        if (g < 40) {
#pragma unroll
            for (int i = 0; i < 4; i++)
#pragma unroll
                for (int j = 0; j < 4; j++)
                    h0s[(ty * 4 + i) * H0S + g * 4 + j] = acc[i][j];
        }
        __syncthreads();
    }

    for (int e = tid; e < 512; e += 256) {
        int o = e >> 3, p = e & 7;
        float ss = s1s[o], oo = o1s[o];
        float m = -FINF;
#pragma unroll
        for (int kk = 0; kk < KNN; kk++) {
            float v = lrelu(fmaf(h0s[o * H0S + p * 20 + kk], ss, oo));
            m = fmaxf(m, v);
        }
        g_xc[((long)(b * 192 + outrow + o)) * NPTS + n0 + p] = m;
    }
}

// ---------------- small reductions ----------------
__global__ void k_gred(int width) {
    int e = blockIdx.x * 256 + threadIdx.x;
    if (e >= BATCH * 1024) return;
    const float* p = g_gpart + (long)e * width;
    float m = -FINF;
    for (int t = 0; t < width; t++) m = fmaxf(m, p[t]);
    g_g[e] = m;
}

__global__ void k_gterm(const float* __restrict__ wf1) {
    int e = blockIdx.x * 256 + threadIdx.x;
    if (e >= BATCH * 512) return;
    int b = e / 512, mo = e - b * 512;
    const float* w = wf1 + (long)mo * 1216 + 192;
    const float* gg = g_g + b * 1024;
    float acc = 0.f;
    for (int c = 0; c < 1024; c++) acc = fmaf(w[c], gg[c], acc);
    g_gterm[e] = acc;
}

// ---------------- host orchestration ----------------
#define EDGE2_SMEM ((4096 + 64 * H0S + 512 + 4 * 64) * 4 + 160 * 4)

extern "C" void kernel_launch(void* const* d_in, const int* in_sizes, int n_in,
                              void* d_out, int out_size) {
    const float* x    = (const float*)d_in[0];
    const float* w1_0 = (const float*)d_in[1];
    const float* s1_0 = (const float*)d_in[2];
    const float* o1_0 = (const float*)d_in[3];
    const float* w1_1 = (const float*)d_in[4];
    const float* s1_1 = (const float*)d_in[5];
    const float* o1_1 = (const float*)d_in[6];
    const float* w2_0 = (const float*)d_in[7];
    const float* s2_0 = (const float*)d_in[8];
    const float* o2_0 = (const float*)d_in[9];
    const float* w2_1 = (const float*)d_in[10];
    const float* s2_1 = (const float*)d_in[11];
    const float* o2_1 = (const float*)d_in[12];
    const float* w3_0 = (const float*)d_in[13];
    const float* s3_0 = (const float*)d_in[14];
    const float* o3_0 = (const float*)d_in[15];
    const float* w3_1 = (const float*)d_in[16];
    const float* s3_1 = (const float*)d_in[17];
    const float* o3_1 = (const float*)d_in[18];
    const float* w4   = (const float*)d_in[19];
    const float* b4   = (const float*)d_in[20];
    const float* wf1  = (const float*)d_in[21];
    const float* sf1  = (const float*)d_in[22];
    const float* of1  = (const float*)d_in[23];
    const float* wf2  = (const float*)d_in[24];
    const float* sf2  = (const float*)d_in[25];
    const float* of2  = (const float*)d_in[26];
    const float* wf3  = (const float*)d_in[27];
    float* out = (float*)d_out;
    (void)in_sizes; (void)n_in; (void)out_size;

    float *p_xc, *p_uv, *p_w2, *p_gterm, *p_h1, *p_h2, *p_gpart;
    cudaGetSymbolAddress((void**)&p_xc,    g_xc);
    cudaGetSymbolAddress((void**)&p_uv,    g_uv);
    cudaGetSymbolAddress((void**)&p_w2,    g_w2);
    cudaGetSymbolAddress((void**)&p_gpart, g_gpart);
    cudaGetSymbolAddress((void**)&p_gterm, g_gterm);
    cudaGetSymbolAddress((void**)&p_h1,    g_h1);
    cudaGetSymbolAddress((void**)&p_h2,    g_h2);

    cudaFuncSetAttribute(k_edge2, cudaFuncAttributeMaxDynamicSharedMemorySize, EDGE2_SMEM);

    dim3 knnG(NPTS / 8, BATCH);
    dim3 edgeG(NPTS / 8, BATCH);
    dim3 uvtG(4, 128, BATCH);
    dim3 simG(32, 32, BATCH);

    // ---- block 1: knn_euclid(x) + edge_conv1 -> xc[0:64) ----
    k_knn_euclid<<<knnG, 256>>>(x);
    k_w2prep<<<3, 256>>>(w1_0, 6);
    k_gemm<<<dim3(64, 2, BATCH), 256>>>(p_w2, 0, 6, 1, 0, x, (long)6 * NPTS,
                                        p_uv, (long)128 * NPTS, 128, 6,
                                        nullptr, nullptr, nullptr, 0, 0);
    k_uvt<<<uvtG, 256>>>();
    k_edge2<<<edgeG, 256, EDGE2_SMEM>>>(w1_1, s1_0, o1_0, s1_1, o1_1, 0);

    // ---- block 2: knn_cosine(x1) via WMMA + edge_conv2 -> xc[64:128) ----
    k_xsplit<<<dim3(16, BATCH), 256>>>(0);
    k_sim_wmma<<<simG, 256>>>();
    k_topk_dmat<<<knnG, 256>>>();
    k_w2prep<<<32, 256>>>(w2_0, 64);
    k_gemm_big<<<dim3(32, 1, BATCH), 256>>>(p_w2, 0, 64, 0, 0, p_xc, (long)192 * NPTS,
                                            p_uv, (long)128 * NPTS, 128, 64,
                                            nullptr, nullptr, nullptr, 0, 0, nullptr);
    k_uvt<<<uvtG, 256>>>();
    k_edge2<<<edgeG, 256, EDGE2_SMEM>>>(w2_1, s2_0, o2_0, s2_1, o2_1, 64);

    // ---- block 3: knn_cosine(x2) via WMMA + edge_conv3 -> xc[128:192) ----
    k_xsplit<<<dim3(16, BATCH), 256>>>(64);
    k_sim_wmma<<<simG, 256>>>();
    k_topk_dmat<<<knnG, 256>>>();
    k_w2prep<<<32, 256>>>(w3_0, 64);
    k_gemm_big<<<dim3(32, 1, BATCH), 256>>>(p_w2, 0, 64, 0, 0, p_xc + (long)64 * NPTS, (long)192 * NPTS,
                                            p_uv, (long)128 * NPTS, 128, 64,
                                            nullptr, nullptr, nullptr, 0, 0, nullptr);
    k_uvt<<<uvtG, 256>>>();
    k_edge2<<<edgeG, 256, EDGE2_SMEM>>>(w3_1, s3_0, o3_0, s3_1, o3_1, 128);

    // ---- head: w4 + fused global max-pool, gterm, wf1 -> wf2 -> wf3 ----
    k_gemm_big<<<dim3(32, 8, BATCH), 256>>>(w4, 0, 192, 0, 0, p_xc, (long)192 * NPTS,
                                            nullptr, 0, 1024, 192,
                                            nullptr, nullptr, b4, 1, 0, p_gpart);
    k_gred<<<16, 256>>>(32);
    k_gterm<<<8, 256>>>(wf1);
    k_gemm_big<<<dim3(32, 4, BATCH), 256>>>(wf1, 0, 1216, 0, 0, p_xc, (long)192 * NPTS,
                                            p_h1, (long)512 * NPTS, 512, 192,
                                            p_gterm, sf1, of1, 1, 0, nullptr);
    k_gemm_big<<<dim3(32, 2, BATCH), 256>>>(wf2, 0, 512, 0, 0, p_h1, (long)512 * NPTS,
                                            p_h2, (long)256 * NPTS, 256, 512,
                                            nullptr, sf2, of2, 1, 0, nullptr);
    k_gemm<<<dim3(64, 1, BATCH), 256>>>(wf3, 0, 256, 1, 0, p_h2, (long)256 * NPTS,
                                        out, (long)13 * NPTS, 13, 256,
                                        nullptr, nullptr, nullptr, 0, 0);
}

// round 13
// speedup vs baseline: 1.1839x; 1.1839x over previous
#include <cuda_runtime.h>
#include <math.h>
#include <stdint.h>

#define BATCH 4
#define NPTS  4096
#define KNN   20
#define FINF  __int_as_float(0x7f800000)
#define FULLM 0xffffffffu
#define U64MAX 0xffffffffffffffffull

typedef unsigned long long u64;

// ---------------- scratch (device globals; no allocations allowed) ----------
__device__ float g_dmat[BATCH * NPTS * NPTS];    // -sim for cosine knn (268MB)
__device__ int   g_idx [BATCH * NPTS * KNN];
__device__ float g_xc  [BATCH * 192 * NPTS];     // concat x1|x2|x3
__device__ float g_xn  [BATCH * 64 * NPTS];      // normalized feats
__device__ float g_uv  [BATCH * 128 * NPTS];     // U rows 0-63, V rows 64-127 (ch-major)
__device__ float g_uvt [BATCH * NPTS * 128];     // point-major copy: uvt[n][c]
__device__ float g_w2  [128 * 64];               // [w0a ; w0b-w0a]
__device__ float g_gpart[BATCH * 1024 * 64];
__device__ float g_g   [BATCH * 1024];
__device__ float g_gterm[BATCH * 512];
__device__ float g_h1  [BATCH * 512 * NPTS];
__device__ float g_h2  [BATCH * 256 * NPTS];

__device__ __forceinline__ float lrelu(float v) { return v >= 0.f ? v : 0.2f * v; }

__device__ __forceinline__ u64 splat2(float a) {
    u64 r;
    unsigned int ai = __float_as_uint(a);
    asm("mov.b64 %0, {%1, %1};" : "=l"(r) : "r"(ai));
    return r;
}
__device__ __forceinline__ void fma2(u64& d, u64 a, u64 b) {
    asm("fma.rn.f32x2 %0, %1, %2, %0;" : "+l"(d) : "l"(a), "l"(b));
}
__device__ __forceinline__ void unpack2(u64 v, float& lo, float& hi) {
    unsigned int l, h;
    asm("mov.b64 {%0, %1}, %2;" : "=r"(l), "=r"(h) : "l"(v));
    lo = __uint_as_float(l); hi = __uint_as_float(h);
}

// ---------------- u64 key top-k machinery ----------------
__device__ __forceinline__ u64 fkey(float d, int j) {
    unsigned int u = __float_as_uint(d);
    u = (u & 0x80000000u) ? ~u : (u | 0x80000000u);
    return ((u64)u << 32) | (unsigned int)j;
}

#define INS5(key) do {                                              \
    u64 _k = (key);                                                 \
    if (_k < c4) {                                                  \
        if (_k < c3) { c4 = c3;                                     \
            if (_k < c2) { c3 = c2;                                 \
                if (_k < c1) { c2 = c1;                             \
                    if (_k < c0) { c1 = c0; c0 = _k; } else c1 = _k;\
                } else c2 = _k;                                     \
            } else c3 = _k;                                         \
        } else c4 = _k;                                             \
    }                                                               \
} while (0)

__device__ __forceinline__ u64 warp_min_u64(u64 v) {
#pragma unroll
    for (int off = 16; off > 0; off >>= 1) {
        u64 o = __shfl_xor_sync(FULLM, v, off);
        v = (o < v) ? o : v;
    }
    return v;
}

__device__ __forceinline__ u64 tk5_merge(u64& c0, u64& c1, u64& c2, u64& c3, u64& c4,
                                         int lane, int* outrow, bool& need2) {
    int pops = 0;
    u64 w = 0;
#pragma unroll 1
    for (int r = 0; r < KNN; r++) {
        w = warp_min_u64(c0);
        if (c0 == w) { c0 = c1; c1 = c2; c2 = c3; c3 = c4; c4 = U64MAX; pops++; }
        if (lane == 0) outrow[r] = (int)(w & 0xffffffffu);
    }
    need2 = __any_sync(FULLM, pops >= 5);
    return w;
}

__device__ __forceinline__ void tk_select_buf(const u64* buf, int m, int lane, int* outrow) {
    u64 k0 = (lane < m) ? buf[lane] : U64MAX;
    u64 k1 = (32 + lane < m) ? buf[32 + lane] : U64MAX;
#pragma unroll 1
    for (int r = 0; r < KNN; r++) {
        u64 lm = (k0 < k1) ? k0 : k1;
        u64 w = warp_min_u64(lm);
        if (k0 == w) k0 = U64MAX;
        else if (k1 == w) k1 = U64MAX;
        if (lane == 0) outrow[r] = (int)(w & 0xffffffffu);
    }
}

// ---------------- kNN euclid (C=6, warp per query) ----------------
__global__ __launch_bounds__(256)
void k_knn_euclid(const float* __restrict__ x) {
    __shared__ u64 sbuf[8][64];
    int b = blockIdx.y;
    int warp = threadIdx.x >> 5, lane = threadIdx.x & 31;
    int i = blockIdx.x * 8 + warp;
    const float* xb = x + b * 6 * NPTS;
    float xi[6];
#pragma unroll
    for (int c = 0; c < 6; c++) xi[c] = xb[c * NPTS + i];
    float sqi = 0.f;
#pragma unroll
    for (int c = 0; c < 6; c++) sqi = fmaf(xi[c], xi[c], sqi);

    u64 c0 = U64MAX, c1 = U64MAX, c2 = U64MAX, c3 = U64MAX, c4 = U64MAX;
    for (int tblk = 0; tblk < NPTS; tblk += 128) {
        int j0 = tblk + lane * 4;
        float4 row[6];
#pragma unroll
        for (int c = 0; c < 6; c++) row[c] = *(const float4*)&xb[c * NPTS + j0];
        float d0 = sqi, d1 = sqi, d2 = sqi, d3 = sqi;
#pragma unroll
        for (int c = 0; c < 6; c++) {
            d0 = fmaf(row[c].x - 2.f * xi[c], row[c].x, d0);
            d1 = fmaf(row[c].y - 2.f * xi[c], row[c].y, d1);
            d2 = fmaf(row[c].z - 2.f * xi[c], row[c].z, d2);
            d3 = fmaf(row[c].w - 2.f * xi[c], row[c].w, d3);
        }
        INS5(fkey(d0, j0));
        INS5(fkey(d1, j0 + 1));
        INS5(fkey(d2, j0 + 2));
        INS5(fkey(d3, j0 + 3));
    }
    int* outrow = g_idx + (b * NPTS + i) * KNN;
    bool need2;
    u64 Tp = tk5_merge(c0, c1, c2, c3, c4, lane, outrow, need2);

    if (need2) {
        u64* buf = sbuf[warp];
        int base = 0;
        for (int tblk = 0; tblk < NPTS; tblk += 128) {
            int j0 = tblk + lane * 4;
            float4 row[6];
#pragma unroll
            for (int c = 0; c < 6; c++) row[c] = *(const float4*)&xb[c * NPTS + j0];
            float dd[4] = {sqi, sqi, sqi, sqi};
#pragma unroll
            for (int c = 0; c < 6; c++) {
                dd[0] = fmaf(row[c].x - 2.f * xi[c], row[c].x, dd[0]);
                dd[1] = fmaf(row[c].y - 2.f * xi[c], row[c].y, dd[1]);
                dd[2] = fmaf(row[c].z - 2.f * xi[c], row[c].z, dd[2]);
                dd[3] = fmaf(row[c].w - 2.f * xi[c], row[c].w, dd[3]);
            }
#pragma unroll
            for (int q = 0; q < 4; q++) {
                u64 k = fkey(dd[q], j0 + q);
                bool p = (k <= Tp);
                unsigned m = __ballot_sync(FULLM, p);
                int pos = base + __popc(m & ((1u << lane) - 1u));
                if (p && pos < 64) buf[pos] = k;
                base += __popc(m);
            }
        }
        __syncwarp();
        tk_select_buf(buf, base < 64 ? base : 64, lane, outrow);
    }
}

// ---------------- top-k from materialized (-sim) matrix (warp per row) ------
__global__ __launch_bounds__(256)
void k_topk_dmat() {
    __shared__ u64 sbuf[8][64];
    int b = blockIdx.y;
    int warp = threadIdx.x >> 5, lane = threadIdx.x & 31;
    int i = blockIdx.x * 8 + warp;
    const float* row = g_dmat + ((long)(b * NPTS + i)) * NPTS;

    u64 c0 = U64MAX, c1 = U64MAX, c2 = U64MAX, c3 = U64MAX, c4 = U64MAX;
    for (int tblk = 0; tblk < NPTS; tblk += 128) {
        int j0 = tblk + lane * 4;
        float4 v = *(const float4*)&row[j0];
        INS5(fkey(v.x, j0));
        INS5(fkey(v.y, j0 + 1));
        INS5(fkey(v.z, j0 + 2));
        INS5(fkey(v.w, j0 + 3));
    }
    int* outrow = g_idx + (b * NPTS + i) * KNN;
    bool need2;
    u64 Tp = tk5_merge(c0, c1, c2, c3, c4, lane, outrow, need2);

    if (need2) {
        u64* buf = sbuf[warp];
        int base = 0;
        for (int tblk = 0; tblk < NPTS; tblk += 128) {
            int j0 = tblk + lane * 4;
            float4 v = *(const float4*)&row[j0];
            u64 kk[4] = {fkey(v.x, j0), fkey(v.y, j0 + 1), fkey(v.z, j0 + 2), fkey(v.w, j0 + 3)};
#pragma unroll
            for (int q = 0; q < 4; q++) {
                bool p = (kk[q] <= Tp);
                unsigned m = __ballot_sync(FULLM, p);
                int pos = base + __popc(m & ((1u << lane) - 1u));
                if (p && pos < 64) buf[pos] = kk[q];
                base += __popc(m);
            }
        }
        __syncwarp();
        tk_select_buf(buf, base < 64 ? base : 64, lane, outrow);
    }
}

// ---------------- channel-wise L2 normalize (64ch) ----------------
__global__ void k_normalize(int srcrow) {
    int b = blockIdx.y;
    int n = blockIdx.x * 256 + threadIdx.x;
    const float* src = g_xc + ((long)b * 192 + srcrow) * NPTS;
    float s = 0.f;
    for (int c = 0; c < 64; c++) { float v = src[c * NPTS + n]; s = fmaf(v, v, s); }
    float inv = 1.f / (sqrtf(s) + 1e-8f);
    float* dst = g_xn + (long)b * 64 * NPTS;
    for (int c = 0; c < 64; c++) dst[c * NPTS + n] = src[c * NPTS + n] * inv;
}

// ---------------- build W2 = [w0a ; w0b - w0a] ----------------
__global__ void k_w2prep(const float* __restrict__ w0, int C) {
    int e = blockIdx.x * 256 + threadIdx.x;
    if (e >= 128 * C) return;
    int o = e / C, c = e % C;
    float val = (o < 64) ? w0[o * (2 * C) + c]
                         : (w0[(o - 64) * (2 * C) + C + c] - w0[(o - 64) * (2 * C) + c]);
    g_w2[o * C + c] = val;
}

// ---------------- transpose g_uv (ch-major) -> g_uvt (point-major) ----------
__global__ void k_uvt() {
    __shared__ float t[32][33];
    int b = blockIdx.z;
    int cb = blockIdx.x * 32, nb = blockIdx.y * 32;
    int tx = threadIdx.x & 31, ty = threadIdx.x >> 5;  // ty 0..7
    const float* src = g_uv + (long)b * 128 * NPTS;
    float* dst = g_uvt + (long)b * NPTS * 128;
#pragma unroll
    for (int k = 0; k < 4; k++)
        t[ty + 8 * k][tx] = src[(long)(cb + ty + 8 * k) * NPTS + nb + tx];
    __syncthreads();
#pragma unroll
    for (int k = 0; k < 4; k++)
        dst[(long)(nb + ty + 8 * k) * 128 + cb + tx] = t[tx][ty + 8 * k];
}

// ---------------- mirror lower-triangle blocks of dmat from upper -----------
// 496 blocks/batch: block pair (bm > bn); dst[bm-block][bn-block] = src^T.
__global__ void k_mirror() {
    __shared__ float t[32][33];
    int b = blockIdx.z;
    int id = blockIdx.x;
    int bm = (int)((sqrtf(8.f * id + 1.f) + 1.f) * 0.5f);
    while (bm * (bm - 1) / 2 > id) bm--;
    while ((bm + 1) * bm / 2 <= id) bm++;
    int bn = id - bm * (bm - 1) / 2;          // bn < bm
    int tx = threadIdx.x & 31, ty = threadIdx.x >> 5;   // ty 0..7
    float* dm = g_dmat + (long)b * NPTS * NPTS;
    int sr = bn * 128, sc = bm * 128;         // source (upper) block origin
#pragma unroll 1
    for (int si = 0; si < 4; si++) {
#pragma unroll 1
        for (int sj = 0; sj < 4; sj++) {
#pragma unroll
            for (int k = 0; k < 4; k++)
                t[ty + 8 * k][tx] = dm[(long)(sr + si * 32 + ty + 8 * k) * NPTS + sc + sj * 32 + tx];
            __syncthreads();
#pragma unroll
            for (int k = 0; k < 4; k++)
                dm[(long)(sc + sj * 32 + ty + 8 * k) * NPTS + sr + si * 32 + tx] = t[tx][ty + 8 * k];
            __syncthreads();
        }
    }
}

// ---------------- post-op ----------------
__device__ __forceinline__ float gemm_post(float v, int gm, int b, int M,
                                           const float* addrow, const float* s,
                                           const float* o, int act, int negate) {
    if (addrow) v += addrow[b * M + gm];
    if (s) v *= s[gm];
    if (o) v += o[gm];
    if (act) v = lrelu(v);
    if (negate) v = -v;
    return v;
}

// ---------------- big GEMM: 128x128 tile, 8x8/thread, fma.f32x2 -------------
// sym=1: grid.x = T*(T+1)/2 upper-triangle tiles (bx >= by); normal writeback.
__global__ __launch_bounds__(256, 2)
void k_gemm_big(const float* __restrict__ A, long a_bs, int as_m, long as_k, int a_colmajor,
                const float* __restrict__ X, long x_bs,
                float* __restrict__ Y, long y_bs,
                int M, int K,
                const float* __restrict__ addrow,
                const float* __restrict__ s, const float* __restrict__ o,
                int act, int negate,
                float* __restrict__ ypart, int sym) {
    __shared__ float As[16][128];
    __shared__ float Xs[16][128];
    int b = blockIdx.z;
    int bx = blockIdx.x, by = blockIdx.y;
    if (sym) {
        int id = blockIdx.x;
        int r = (int)((sqrtf(8.f * id + 1.f) - 1.f) * 0.5f);
        while ((r + 1) * (r + 2) / 2 <= id) r++;
        while (r * (r + 1) / 2 > id) r--;
        bx = r; by = id - r * (r + 1) / 2;   // bx >= by
    }
    int m0 = by * 128, n0 = bx * 128;
    const float* Ab = A + (long)b * a_bs;
    const float* Xb = X + (long)b * x_bs;
    int tid = threadIdx.x;
    int ty = tid >> 4, tx = tid & 15;

    u64 acc[8][4];
#pragma unroll
    for (int i = 0; i < 8; i++)
#pragma unroll
        for (int j = 0; j < 4; j++) acc[i][j] = 0ull;

    for (int k0 = 0; k0 < K; k0 += 16) {
        if (a_colmajor) {
            for (int e = tid; e < 512; e += 256) {
                int kk = e >> 5, m4 = e & 31;
                *(float4*)&As[kk][m4 * 4] =
                    *(const float4*)&Ab[(long)(k0 + kk) * as_k + (m0 + m4 * 4)];
            }
        } else {
            for (int e = tid; e < 2048; e += 256) {
                int mm = e >> 4, kk = e & 15;
                int gm = m0 + mm;
                As[kk][mm] = (gm < M) ? Ab[(long)gm * as_m + (k0 + kk)] : 0.f;
            }
        }
        for (int e = tid; e < 512; e += 256) {
            int kk = e >> 5, n4 = e & 31;
            *(float4*)&Xs[kk][n4 * 4] =
                *(const float4*)&Xb[(long)(k0 + kk) * NPTS + n0 + n4 * 4];
        }
        __syncthreads();
#pragma unroll
        for (int kk = 0; kk < 16; kk++) {
            float a[8];
            *(float4*)a       = *(float4*)&As[kk][ty * 8];
            *(float4*)(a + 4) = *(float4*)&As[kk][ty * 8 + 4];
            u64 xv[4];
#pragma unroll
            for (int j = 0; j < 4; j++) xv[j] = *(u64*)&Xs[kk][tx * 8 + j * 2];
#pragma unroll
            for (int i = 0; i < 8; i++) {
                u64 ai = splat2(a[i]);
#pragma unroll
                for (int j = 0; j < 4; j++) fma2(acc[i][j], ai, xv[j]);
            }
        }
        __syncthreads();
    }

    if (ypart) {  // fused global max-pool across this N-tile
        float* red = &As[0][0];
#pragma unroll
        for (int i = 0; i < 8; i++) {
            int gm = m0 + ty * 8 + i;
            int gmc = gm < M ? gm : 0;
            float mloc = -FINF;
#pragma unroll
            for (int j = 0; j < 4; j++) {
                float lo, hi;
                unpack2(acc[i][j], lo, hi);
                lo = gemm_post(lo, gmc, b, M, addrow, s, o, act, negate);
                hi = gemm_post(hi, gmc, b, M, addrow, s, o, act, negate);
                mloc = fmaxf(mloc, fmaxf(lo, hi));
            }
            red[(ty * 8 + i) * 16 + tx] = mloc;
        }
        __syncthreads();
        if (tid < 128) {
            float m = -FINF;
            for (int q = 0; q < 16; q++) m = fmaxf(m, red[tid * 16 + q]);
            int gm = m0 + tid;
            if (gm < M) ypart[((long)(b * M + gm)) * gridDim.x + blockIdx.x] = m;
        }
    } else {
#pragma unroll
        for (int i = 0; i < 8; i++) {
            int gm = m0 + ty * 8 + i;
            if (gm >= M) continue;
            float out8[8];
#pragma unroll
            for (int j = 0; j < 4; j++) {
                float lo, hi;
                unpack2(acc[i][j], lo, hi);
                out8[j * 2]     = gemm_post(lo, gm, b, M, addrow, s, o, act, negate);
                out8[j * 2 + 1] = gemm_post(hi, gm, b, M, addrow, s, o, act, negate);
            }
            float* dst = Y + (long)b * y_bs + (long)gm * NPTS + n0 + tx * 8;
            *(float4*)dst       = *(float4*)out8;
            *(float4*)(dst + 4) = *(float4*)(out8 + 4);
        }
    }
}

// ---------------- small-case GEMM (K=6 or M=13): 64x64 tile ----------------
#define BM 64
#define BN 64
#define BK 16

__global__ void k_gemm(const float* __restrict__ A, long a_bs, int as_m, long as_k, int a_colmajor,
                       const float* __restrict__ X, long x_bs,
                       float* __restrict__ Y, long y_bs,
                       int M, int K,
                       const float* __restrict__ addrow,
                       const float* __restrict__ s, const float* __restrict__ o,
                       int act, int negate) {
    __shared__ float As[BK][BM + 4];
    __shared__ float Xs[BK][BN + 4];
    int b = blockIdx.z;
    int m0 = blockIdx.y * BM, n0 = blockIdx.x * BN;
    const float* Ab = A + (long)b * a_bs;
    const float* Xb = X + (long)b * x_bs;
    int tid = threadIdx.x;
    int ty = tid >> 4, tx = tid & 15;
    float acc[4][4] = {};
    for (int k0 = 0; k0 < K; k0 += BK) {
        for (int e = tid; e < BK * BM; e += 256) {
            int mm = e >> 4, kk = e & 15;
            int gm = m0 + mm, gk = k0 + kk;
            As[kk][mm] = (gk < K && gm < M) ? Ab[(long)gm * as_m + (long)gk * as_k] : 0.f;
        }
        for (int e = tid; e < BK * BN; e += 256) {
            int kk = e >> 6, nn = e & 63;
            int gk = k0 + kk;
            Xs[kk][nn] = (gk < K) ? Xb[(long)gk * NPTS + n0 + nn] : 0.f;
        }
        __syncthreads();
#pragma unroll
        for (int kk = 0; kk < BK; kk++) {
            float a[4], xv[4];
#pragma unroll
            for (int i = 0; i < 4; i++) a[i] = As[kk][ty * 4 + i];
#pragma unroll
            for (int j = 0; j < 4; j++) xv[j] = Xs[kk][tx * 4 + j];
#pragma unroll
            for (int i = 0; i < 4; i++)
#pragma unroll
                for (int j = 0; j < 4; j++)
                    acc[i][j] = fmaf(a[i], xv[j], acc[i][j]);
        }
        __syncthreads();
    }
#pragma unroll
    for (int i = 0; i < 4; i++) {
        int gm = m0 + ty * 4 + i;
        if (gm >= M) continue;
#pragma unroll
        for (int j = 0; j < 4; j++) {
            float v = gemm_post(acc[i][j], gm, b, M, addrow, s, o, act, negate);
            Y[(long)b * y_bs + (long)gm * NPTS + n0 + tx * 4 + j] = v;
        }
    }
}

// ---------------- edge-conv 2nd half: gather (point-major) + GEMM + max ----
#define H0S 164   // padded col stride (160 cols)

__global__ void k_edge2(const float* __restrict__ w1,
                        const float* __restrict__ s0, const float* __restrict__ o0,
                        const float* __restrict__ s1, const float* __restrict__ o1,
                        int outrow) {
    extern __shared__ float sm[];
    float* w1s = sm;                  // 64*64   [o][c]
    float* h0s = w1s + 4096;          // 64*H0S  [c][col] -> overwritten by H1 [o][col]
    float* vcs = h0s + 64 * H0S;      // 8*64    [p][c] center V values
    float* s0s = vcs + 512;
    float* o0s = s0s + 64;
    float* s1s = o0s + 64;
    float* o1s = s1s + 64;
    int*   idxs = (int*)(o1s + 64);   // 160

    int tid = threadIdx.x;
    int b = blockIdx.y;
    int n0 = blockIdx.x * 8;
    const float* uvt = g_uvt + (long)b * NPTS * 128;

    for (int e = tid; e < 4096; e += 256) w1s[e] = w1[e];
    if (tid < 64) { s0s[tid] = s0[tid]; o0s[tid] = o0[tid]; s1s[tid] = s1[tid]; o1s[tid] = o1[tid]; }
    for (int e = tid; e < 160; e += 256)
        idxs[e] = g_idx[(b * NPTS + n0 + e / 20) * KNN + e % 20];
    if (tid < 128) {
        int p = tid >> 4, cq = tid & 15;
        *(((float4*)vcs) + tid) = *(const float4*)&uvt[(long)(n0 + p) * 128 + 64 + cq * 4];
    }
    __syncthreads();

    for (int e = tid; e < 16 * 160; e += 256) {
        int cq = e / 160, col = e - cq * 160;
        int p = col / 20;
        int j = idxs[col];
        float4 u = *(const float4*)&uvt[(long)j * 128 + cq * 4];
        float4 vv = *(((const float4*)vcs) + p * 16 + cq);
        int c = cq * 4;
        h0s[(c + 0) * H0S + col] = lrelu(fmaf(u.x + vv.x, s0s[c + 0], o0s[c + 0]));
        h0s[(c + 1) * H0S + col] = lrelu(fmaf(u.y + vv.y, s0s[c + 1], o0s[c + 1]));
        h0s[(c + 2) * H0S + col] = lrelu(fmaf(u.z + vv.z, s0s[c + 2], o0s[c + 2]));
        h0s[(c + 3) * H0S + col] = lrelu(fmaf(u.w + vv.w, s0s[c + 3], o0s[c + 3]));
    }
    __syncthreads();

    int ty = tid >> 4, tx = tid & 15;
    for (int iter = 0; iter < 3; iter++) {
        int g = tx + iter * 16;
        float acc[4][4] = {};
        if (g < 40) {
#pragma unroll
            for (int c4 = 0; c4 < 16; c4++) {
                float4 h[4], w[4];
#pragma unroll
                for (int q = 0; q < 4; q++) h[q] = *(const float4*)&h0s[(c4 * 4 + q) * H0S + g * 4];
#pragma unroll
                for (int q = 0; q < 4; q++) w[q] = *(const float4*)&w1s[(ty * 4 + q) * 64 + c4 * 4];
#pragma unroll
                for (int i = 0; i < 4; i++) {
                    acc[i][0] = fmaf(w[i].x, h[0].x, acc[i][0]);
                    acc[i][0] = fmaf(w[i].y, h[1].x, acc[i][0]);
                    acc[i][0] = fmaf(w[i].z, h[2].x, acc[i][0]);
                    acc[i][0] = fmaf(w[i].w, h[3].x, acc[i][0]);
                    acc[i][1] = fmaf(w[i].x, h[0].y, acc[i][1]);
                    acc[i][1] = fmaf(w[i].y, h[1].y, acc[i][1]);
                    acc[i][1] = fmaf(w[i].z, h[2].y, acc[i][1]);
                    acc[i][1] = fmaf(w[i].w, h[3].y, acc[i][1]);
                    acc[i][2] = fmaf(w[i].x, h[0].z, acc[i][2]);
                    acc[i][2] = fmaf(w[i].y, h[1].z, acc[i][2]);
                    acc[i][2] = fmaf(w[i].z, h[2].z, acc[i][2]);
                    acc[i][2] = fmaf(w[i].w, h[3].z, acc[i][2]);
                    acc[i][3] = fmaf(w[i].x, h[0].w, acc[i][3]);
                    acc[i][3] = fmaf(w[i].y, h[1].w, acc[i][3]);
                    acc[i][3] = fmaf(w[i].z, h[2].w, acc[i][3]);
                    acc[i][3] = fmaf(w[i].w, h[3].w, acc[i][3]);
                }
            }
        }
        __syncthreads();
        if (g < 40) {
#pragma unroll
            for (int i = 0; i < 4; i++)
#pragma unroll
                for (int j = 0; j < 4; j++)
                    h0s[(ty * 4 + i) * H0S + g * 4 + j] = acc[i][j];
        }
        __syncthreads();
    }

    for (int e = tid; e < 512; e += 256) {
        int o = e >> 3, p = e & 7;
        float ss = s1s[o], oo = o1s[o];
        float m = -FINF;
#pragma unroll
        for (int kk = 0; kk < KNN; kk++) {
            float v = lrelu(fmaf(h0s[o * H0S + p * 20 + kk], ss, oo));
            m = fmaxf(m, v);
        }
        g_xc[((long)(b * 192 + outrow + o)) * NPTS + n0 + p] = m;
    }
}

// ---------------- small reductions ----------------
__global__ void k_gred(int width) {
    int e = blockIdx.x * 256 + threadIdx.x;
    if (e >= BATCH * 1024) return;
    const float* p = g_gpart + (long)e * width;
    float m = -FINF;
    for (int t = 0; t < width; t++) m = fmaxf(m, p[t]);
    g_g[e] = m;
}

__global__ void k_gterm(const float* __restrict__ wf1) {
    int e = blockIdx.x * 256 + threadIdx.x;
    if (e >= BATCH * 512) return;
    int b = e / 512, mo = e - b * 512;
    const float* w = wf1 + (long)mo * 1216 + 192;
    const float* gg = g_g + b * 1024;
    float acc = 0.f;
    for (int c = 0; c < 1024; c++) acc = fmaf(w[c], gg[c], acc);
    g_gterm[e] = acc;
}

// ---------------- host orchestration ----------------
#define EDGE2_SMEM ((4096 + 64 * H0S + 512 + 4 * 64) * 4 + 160 * 4)
#define SIM_TILES (32 * 33 / 2)
#define MIR_TILES (32 * 31 / 2)

extern "C" void kernel_launch(void* const* d_in, const int* in_sizes, int n_in,
                              void* d_out, int out_size) {
    const float* x    = (const float*)d_in[0];
    const float* w1_0 = (const float*)d_in[1];
    const float* s1_0 = (const float*)d_in[2];
    const float* o1_0 = (const float*)d_in[3];
    const float* w1_1 = (const float*)d_in[4];
    const float* s1_1 = (const float*)d_in[5];
    const float* o1_1 = (const float*)d_in[6];
    const float* w2_0 = (const float*)d_in[7];
    const float* s2_0 = (const float*)d_in[8];
    const float* o2_0 = (const float*)d_in[9];
    const float* w2_1 = (const float*)d_in[10];
    const float* s2_1 = (const float*)d_in[11];
    const float* o2_1 = (const float*)d_in[12];
    const float* w3_0 = (const float*)d_in[13];
    const float* s3_0 = (const float*)d_in[14];
    const float* o3_0 = (const float*)d_in[15];
    const float* w3_1 = (const float*)d_in[16];
    const float* s3_1 = (const float*)d_in[17];
    const float* o3_1 = (const float*)d_in[18];
    const float* w4   = (const float*)d_in[19];
    const float* b4   = (const float*)d_in[20];
    const float* wf1  = (const float*)d_in[21];
    const float* sf1  = (const float*)d_in[22];
    const float* of1  = (const float*)d_in[23];
    const float* wf2  = (const float*)d_in[24];
    const float* sf2  = (const float*)d_in[25];
    const float* of2  = (const float*)d_in[26];
    const float* wf3  = (const float*)d_in[27];
    float* out = (float*)d_out;
    (void)in_sizes; (void)n_in; (void)out_size;

    float *p_xc, *p_xn, *p_uv, *p_w2, *p_gterm, *p_h1, *p_h2, *p_gpart, *p_dmat;
    cudaGetSymbolAddress((void**)&p_dmat,  g_dmat);
    cudaGetSymbolAddress((void**)&p_xc,    g_xc);
    cudaGetSymbolAddress((void**)&p_xn,    g_xn);
    cudaGetSymbolAddress((void**)&p_uv,    g_uv);
    cudaGetSymbolAddress((void**)&p_w2,    g_w2);
    cudaGetSymbolAddress((void**)&p_gpart, g_gpart);
    cudaGetSymbolAddress((void**)&p_gterm, g_gterm);
    cudaGetSymbolAddress((void**)&p_h1,    g_h1);
    cudaGetSymbolAddress((void**)&p_h2,    g_h2);

    cudaFuncSetAttribute(k_edge2, cudaFuncAttributeMaxDynamicSharedMemorySize, EDGE2_SMEM);

    dim3 knnG(NPTS / 8, BATCH);
    dim3 edgeG(NPTS / 8, BATCH);
    dim3 uvtG(4, 128, BATCH);
    dim3 simG(SIM_TILES, 1, BATCH);
    dim3 mirG(MIR_TILES, 1, BATCH);

    // ---- block 1: knn_euclid(x) + edge_conv1 -> xc[0:64) ----
    k_knn_euclid<<<knnG, 256>>>(x);
    k_w2prep<<<3, 256>>>(w1_0, 6);
    k_gemm<<<dim3(64, 2, BATCH), 256>>>(p_w2, 0, 6, 1, 0, x, (long)6 * NPTS,
                                        p_uv, (long)128 * NPTS, 128, 6,
                                        nullptr, nullptr, nullptr, 0, 0);
    k_uvt<<<uvtG, 256>>>();
    k_edge2<<<edgeG, 256, EDGE2_SMEM>>>(w1_1, s1_0, o1_0, s1_1, o1_1, 0);

    // ---- block 2: knn_cosine(x1) sym-GEMM + mirror + edge_conv2 ----
    k_normalize<<<dim3(16, BATCH), 256>>>(0);
    k_gemm_big<<<simG, 256>>>(p_xn, (long)64 * NPTS, 1, NPTS, 1,
                              p_xn, (long)64 * NPTS,
                              p_dmat, (long)NPTS * NPTS, NPTS, 64,
                              nullptr, nullptr, nullptr, 0, 1, nullptr, 1);
    k_mirror<<<mirG, 256>>>();
    k_topk_dmat<<<knnG, 256>>>();
    k_w2prep<<<32, 256>>>(w2_0, 64);
    k_gemm_big<<<dim3(32, 1, BATCH), 256>>>(p_w2, 0, 64, 0, 0, p_xc, (long)192 * NPTS,
                                            p_uv, (long)128 * NPTS, 128, 64,
                                            nullptr, nullptr, nullptr, 0, 0, nullptr, 0);
    k_uvt<<<uvtG, 256>>>();
    k_edge2<<<edgeG, 256, EDGE2_SMEM>>>(w2_1, s2_0, o2_0, s2_1, o2_1, 64);

    // ---- block 3: knn_cosine(x2) sym-GEMM + mirror + edge_conv3 ----
    k_normalize<<<dim3(16, BATCH), 256>>>(64);
    k_gemm_big<<<simG, 256>>>(p_xn, (long)64 * NPTS, 1, NPTS, 1,
                              p_xn, (long)64 * NPTS,
                              p_dmat, (long)NPTS * NPTS, NPTS, 64,
                              nullptr, nullptr, nullptr, 0, 1, nullptr, 1);
    k_mirror<<<mirG, 256>>>();
    k_topk_dmat<<<knnG, 256>>>();
    k_w2prep<<<32, 256>>>(w3_0, 64);
    k_gemm_big<<<dim3(32, 1, BATCH), 256>>>(p_w2, 0, 64, 0, 0, p_xc + (long)64 * NPTS, (long)192 * NPTS,
                                            p_uv, (long)128 * NPTS, 128, 64,
                                            nullptr, nullptr, nullptr, 0, 0, nullptr, 0);
    k_uvt<<<uvtG, 256>>>();
    k_edge2<<<edgeG, 256, EDGE2_SMEM>>>(w3_1, s3_0, o3_0, s3_1, o3_1, 128);

    // ---- head: w4 + fused global max-pool, gterm, wf1 -> wf2 -> wf3 ----
    k_gemm_big<<<dim3(32, 8, BATCH), 256>>>(w4, 0, 192, 0, 0, p_xc, (long)192 * NPTS,
                                            nullptr, 0, 1024, 192,
                                            nullptr, nullptr, b4, 1, 0, p_gpart, 0);
    k_gred<<<16, 256>>>(32);
    k_gterm<<<8, 256>>>(wf1);
    k_gemm_big<<<dim3(32, 4, BATCH), 256>>>(wf1, 0, 1216, 0, 0, p_xc, (long)192 * NPTS,
                                            p_h1, (long)512 * NPTS, 512, 192,
                                            p_gterm, sf1, of1, 1, 0, nullptr, 0);
    k_gemm_big<<<dim3(32, 2, BATCH), 256>>>(wf2, 0, 512, 0, 0, p_h1, (long)512 * NPTS,
                                            p_h2, (long)256 * NPTS, 256, 512,
                                            nullptr, sf2, of2, 1, 0, nullptr, 0);
    k_gemm<<<dim3(64, 1, BATCH), 256>>>(wf3, 0, 256, 1, 0, p_h2, (long)256 * NPTS,
                                        out, (long)13 * NPTS, 13, 256,
                                        nullptr, nullptr, nullptr, 0, 0);
}

// round 14
// speedup vs baseline: 1.2045x; 1.0174x over previous
#include <cuda_runtime.h>
#include <math.h>
#include <stdint.h>

#define BATCH 4
#define NPTS  4096
#define KNN   20
#define FINF  __int_as_float(0x7f800000)
#define FULLM 0xffffffffu
#define U64MAX 0xffffffffffffffffull

typedef unsigned long long u64;

// ---------------- scratch (device globals; no allocations allowed) ----------
__device__ float g_dmat[BATCH * NPTS * NPTS];    // -sim for cosine knn (268MB)
__device__ int   g_idx [BATCH * NPTS * KNN];
__device__ float g_xc  [BATCH * 192 * NPTS];     // concat x1|x2|x3
__device__ float g_xn  [BATCH * 64 * NPTS];      // normalized feats
__device__ float g_uv  [BATCH * 128 * NPTS];     // U rows 0-63, V rows 64-127 (ch-major)
__device__ float g_uvt [BATCH * NPTS * 128];     // point-major copy: uvt[n][c]
__device__ float g_w2  [128 * 64];               // [w0a ; w0b-w0a]
__device__ float g_gpart[BATCH * 1024 * 64];
__device__ float g_g   [BATCH * 1024];
__device__ float g_gterm[BATCH * 512];
__device__ float g_h1  [BATCH * 512 * NPTS];
__device__ float g_h2  [BATCH * 256 * NPTS];

__device__ __forceinline__ float lrelu(float v) { return v >= 0.f ? v : 0.2f * v; }

__device__ __forceinline__ u64 splat2(float a) {
    u64 r;
    unsigned int ai = __float_as_uint(a);
    asm("mov.b64 %0, {%1, %1};" : "=l"(r) : "r"(ai));
    return r;
}
__device__ __forceinline__ void fma2(u64& d, u64 a, u64 b) {
    asm("fma.rn.f32x2 %0, %1, %2, %0;" : "+l"(d) : "l"(a), "l"(b));
}
__device__ __forceinline__ void unpack2(u64 v, float& lo, float& hi) {
    unsigned int l, h;
    asm("mov.b64 {%0, %1}, %2;" : "=r"(l), "=r"(h) : "l"(v));
    lo = __uint_as_float(l); hi = __uint_as_float(h);
}

// ---------------- u64 key top-k machinery ----------------
__device__ __forceinline__ u64 fkey(float d, int j) {
    unsigned int u = __float_as_uint(d);
    u = (u & 0x80000000u) ? ~u : (u | 0x80000000u);
    return ((u64)u << 32) | (unsigned int)j;
}

#define INS5(key) do {                                              \
    u64 _k = (key);                                                 \
    if (_k < c4) {                                                  \
        if (_k < c3) { c4 = c3;                                     \
            if (_k < c2) { c3 = c2;                                 \
                if (_k < c1) { c2 = c1;                             \
                    if (_k < c0) { c1 = c0; c0 = _k; } else c1 = _k;\
                } else c2 = _k;                                     \
            } else c3 = _k;                                         \
        } else c4 = _k;                                             \
    }                                                               \
} while (0)

__device__ __forceinline__ u64 warp_min_u64(u64 v) {
#pragma unroll
    for (int off = 16; off > 0; off >>= 1) {
        u64 o = __shfl_xor_sync(FULLM, v, off);
        v = (o < v) ? o : v;
    }
    return v;
}

__device__ __forceinline__ u64 tk5_merge(u64& c0, u64& c1, u64& c2, u64& c3, u64& c4,
                                         int lane, int* outrow, bool& need2) {
    int pops = 0;
    u64 w = 0;
#pragma unroll 1
    for (int r = 0; r < KNN; r++) {
        w = warp_min_u64(c0);
        if (c0 == w) { c0 = c1; c1 = c2; c2 = c3; c3 = c4; c4 = U64MAX; pops++; }
        if (lane == 0) outrow[r] = (int)(w & 0xffffffffu);
    }
    need2 = __any_sync(FULLM, pops >= 5);
    return w;
}

__device__ __forceinline__ void tk_select_buf(const u64* buf, int m, int lane, int* outrow) {
    u64 k0 = (lane < m) ? buf[lane] : U64MAX;
    u64 k1 = (32 + lane < m) ? buf[32 + lane] : U64MAX;
#pragma unroll 1
    for (int r = 0; r < KNN; r++) {
        u64 lm = (k0 < k1) ? k0 : k1;
        u64 w = warp_min_u64(lm);
        if (k0 == w) k0 = U64MAX;
        else if (k1 == w) k1 = U64MAX;
        if (lane == 0) outrow[r] = (int)(w & 0xffffffffu);
    }
}

// ---------------- kNN euclid (C=6, warp per query) ----------------
__global__ __launch_bounds__(256)
void k_knn_euclid(const float* __restrict__ x) {
    __shared__ u64 sbuf[8][64];
    int b = blockIdx.y;
    int warp = threadIdx.x >> 5, lane = threadIdx.x & 31;
    int i = blockIdx.x * 8 + warp;
    const float* xb = x + b * 6 * NPTS;
    float xi[6];
#pragma unroll
    for (int c = 0; c < 6; c++) xi[c] = xb[c * NPTS + i];
    float sqi = 0.f;
#pragma unroll
    for (int c = 0; c < 6; c++) sqi = fmaf(xi[c], xi[c], sqi);

    u64 c0 = U64MAX, c1 = U64MAX, c2 = U64MAX, c3 = U64MAX, c4 = U64MAX;
    for (int tblk = 0; tblk < NPTS; tblk += 128) {
        int j0 = tblk + lane * 4;
        float4 row[6];
#pragma unroll
        for (int c = 0; c < 6; c++) row[c] = *(const float4*)&xb[c * NPTS + j0];
        float d0 = sqi, d1 = sqi, d2 = sqi, d3 = sqi;
#pragma unroll
        for (int c = 0; c < 6; c++) {
            d0 = fmaf(row[c].x - 2.f * xi[c], row[c].x, d0);
            d1 = fmaf(row[c].y - 2.f * xi[c], row[c].y, d1);
            d2 = fmaf(row[c].z - 2.f * xi[c], row[c].z, d2);
            d3 = fmaf(row[c].w - 2.f * xi[c], row[c].w, d3);
        }
        INS5(fkey(d0, j0));
        INS5(fkey(d1, j0 + 1));
        INS5(fkey(d2, j0 + 2));
        INS5(fkey(d3, j0 + 3));
    }
    int* outrow = g_idx + (b * NPTS + i) * KNN;
    bool need2;
    u64 Tp = tk5_merge(c0, c1, c2, c3, c4, lane, outrow, need2);

    if (need2) {
        u64* buf = sbuf[warp];
        int base = 0;
        for (int tblk = 0; tblk < NPTS; tblk += 128) {
            int j0 = tblk + lane * 4;
            float4 row[6];
#pragma unroll
            for (int c = 0; c < 6; c++) row[c] = *(const float4*)&xb[c * NPTS + j0];
            float dd[4] = {sqi, sqi, sqi, sqi};
#pragma unroll
            for (int c = 0; c < 6; c++) {
                dd[0] = fmaf(row[c].x - 2.f * xi[c], row[c].x, dd[0]);
                dd[1] = fmaf(row[c].y - 2.f * xi[c], row[c].y, dd[1]);
                dd[2] = fmaf(row[c].z - 2.f * xi[c], row[c].z, dd[2]);
                dd[3] = fmaf(row[c].w - 2.f * xi[c], row[c].w, dd[3]);
            }
#pragma unroll
            for (int q = 0; q < 4; q++) {
                u64 k = fkey(dd[q], j0 + q);
                bool p = (k <= Tp);
                unsigned m = __ballot_sync(FULLM, p);
                int pos = base + __popc(m & ((1u << lane) - 1u));
                if (p && pos < 64) buf[pos] = k;
                base += __popc(m);
            }
        }
        __syncwarp();
        tk_select_buf(buf, base < 64 ? base : 64, lane, outrow);
    }
}

// ---------------- top-k from materialized (-sim) matrix (warp per row) ------
__global__ __launch_bounds__(256)
void k_topk_dmat() {
    __shared__ u64 sbuf[8][64];
    int b = blockIdx.y;
    int warp = threadIdx.x >> 5, lane = threadIdx.x & 31;
    int i = blockIdx.x * 8 + warp;
    const float* row = g_dmat + ((long)(b * NPTS + i)) * NPTS;

    u64 c0 = U64MAX, c1 = U64MAX, c2 = U64MAX, c3 = U64MAX, c4 = U64MAX;
    for (int tblk = 0; tblk < NPTS; tblk += 128) {
        int j0 = tblk + lane * 4;
        float4 v = *(const float4*)&row[j0];
        INS5(fkey(v.x, j0));
        INS5(fkey(v.y, j0 + 1));
        INS5(fkey(v.z, j0 + 2));
        INS5(fkey(v.w, j0 + 3));
    }
    int* outrow = g_idx + (b * NPTS + i) * KNN;
    bool need2;
    u64 Tp = tk5_merge(c0, c1, c2, c3, c4, lane, outrow, need2);

    if (need2) {
        u64* buf = sbuf[warp];
        int base = 0;
        for (int tblk = 0; tblk < NPTS; tblk += 128) {
            int j0 = tblk + lane * 4;
            float4 v = *(const float4*)&row[j0];
            u64 kk[4] = {fkey(v.x, j0), fkey(v.y, j0 + 1), fkey(v.z, j0 + 2), fkey(v.w, j0 + 3)};
#pragma unroll
            for (int q = 0; q < 4; q++) {
                bool p = (kk[q] <= Tp);
                unsigned m = __ballot_sync(FULLM, p);
                int pos = base + __popc(m & ((1u << lane) - 1u));
                if (p && pos < 64) buf[pos] = kk[q];
                base += __popc(m);
            }
        }
        __syncwarp();
        tk_select_buf(buf, base < 64 ? base : 64, lane, outrow);
    }
}

// ---------------- channel-wise L2 normalize (64ch) ----------------
__global__ void k_normalize(int srcrow) {
    int b = blockIdx.y;
    int n = blockIdx.x * 256 + threadIdx.x;
    const float* src = g_xc + ((long)b * 192 + srcrow) * NPTS;
    float s = 0.f;
    for (int c = 0; c < 64; c++) { float v = src[c * NPTS + n]; s = fmaf(v, v, s); }
    float inv = 1.f / (sqrtf(s) + 1e-8f);
    float* dst = g_xn + (long)b * 64 * NPTS;
    for (int c = 0; c < 64; c++) dst[c * NPTS + n] = src[c * NPTS + n] * inv;
}

// ---------------- build W2 = [w0a ; w0b - w0a] ----------------
__global__ void k_w2prep(const float* __restrict__ w0, int C) {
    int e = blockIdx.x * 256 + threadIdx.x;
    if (e >= 128 * C) return;
    int o = e / C, c = e % C;
    float val = (o < 64) ? w0[o * (2 * C) + c]
                         : (w0[(o - 64) * (2 * C) + C + c] - w0[(o - 64) * (2 * C) + c]);
    g_w2[o * C + c] = val;
}

// ---------------- transpose g_uv (ch-major) -> g_uvt (point-major) ----------
__global__ void k_uvt() {
    __shared__ float t[32][33];
    int b = blockIdx.z;
    int cb = blockIdx.x * 32, nb = blockIdx.y * 32;
    int tx = threadIdx.x & 31, ty = threadIdx.x >> 5;  // ty 0..7
    const float* src = g_uv + (long)b * 128 * NPTS;
    float* dst = g_uvt + (long)b * NPTS * 128;
#pragma unroll
    for (int k = 0; k < 4; k++)
        t[ty + 8 * k][tx] = src[(long)(cb + ty + 8 * k) * NPTS + nb + tx];
    __syncthreads();
#pragma unroll
    for (int k = 0; k < 4; k++)
        dst[(long)(nb + ty + 8 * k) * 128 + cb + tx] = t[tx][ty + 8 * k];
}

// ---------------- mirror lower-triangle blocks of dmat from upper -----------
__global__ void k_mirror() {
    __shared__ float t[32][33];
    int b = blockIdx.z;
    int id = blockIdx.x;
    int bm = (int)((sqrtf(8.f * id + 1.f) + 1.f) * 0.5f);
    while (bm * (bm - 1) / 2 > id) bm--;
    while ((bm + 1) * bm / 2 <= id) bm++;
    int bn = id - bm * (bm - 1) / 2;          // bn < bm
    int tx = threadIdx.x & 31, ty = threadIdx.x >> 5;   // ty 0..7
    float* dm = g_dmat + (long)b * NPTS * NPTS;
    int sr = bn * 128, sc = bm * 128;         // source (upper) block origin
#pragma unroll 1
    for (int si = 0; si < 4; si++) {
#pragma unroll 1
        for (int sj = 0; sj < 4; sj++) {
#pragma unroll
            for (int k = 0; k < 4; k++)
                t[ty + 8 * k][tx] = dm[(long)(sr + si * 32 + ty + 8 * k) * NPTS + sc + sj * 32 + tx];
            __syncthreads();
#pragma unroll
            for (int k = 0; k < 4; k++)
                dm[(long)(sc + sj * 32 + ty + 8 * k) * NPTS + sr + si * 32 + tx] = t[tx][ty + 8 * k];
            __syncthreads();
        }
    }
}

// ---------------- post-op ----------------
__device__ __forceinline__ float gemm_post(float v, int gm, int b, int M,
                                           const float* addrow, const float* s,
                                           const float* o, int act, int negate) {
    if (addrow) v += addrow[b * M + gm];
    if (s) v *= s[gm];
    if (o) v += o[gm];
    if (act) v = lrelu(v);
    if (negate) v = -v;
    return v;
}

// ---------------- big GEMM: 128x128 tile, 8x8/thread, fma.f32x2 -------------
// Double-buffered smem; X (and col-major A) prefetched into registers.
// sym=1: grid.x = T*(T+1)/2 upper-triangle tiles (bx >= by); normal writeback.
__global__ __launch_bounds__(256, 2)
void k_gemm_big(const float* __restrict__ A, long a_bs, int as_m, long as_k, int a_colmajor,
                const float* __restrict__ X, long x_bs,
                float* __restrict__ Y, long y_bs,
                int M, int K,
                const float* __restrict__ addrow,
                const float* __restrict__ s, const float* __restrict__ o,
                int act, int negate,
                float* __restrict__ ypart, int sym) {
    __shared__ float As[2][16][128];
    __shared__ float Xs[2][16][128];
    int b = blockIdx.z;
    int bx = blockIdx.x, by = blockIdx.y;
    if (sym) {
        int id = blockIdx.x;
        int r = (int)((sqrtf(8.f * id + 1.f) - 1.f) * 0.5f);
        while ((r + 1) * (r + 2) / 2 <= id) r++;
        while (r * (r + 1) / 2 > id) r--;
        bx = r; by = id - r * (r + 1) / 2;   // bx >= by
    }
    int m0 = by * 128, n0 = bx * 128;
    const float* Ab = A + (long)b * a_bs;
    const float* Xb = X + (long)b * x_bs;
    int tid = threadIdx.x;
    int ty = tid >> 4, tx = tid & 15;

    u64 acc[8][4];
#pragma unroll
    for (int i = 0; i < 8; i++)
#pragma unroll
        for (int j = 0; j < 4; j++) acc[i][j] = 0ull;

    int nk = K >> 4;

    // prologue: chunk 0 straight to smem buffer 0
    if (a_colmajor) {
        for (int e = tid; e < 512; e += 256) {
            int kk = e >> 5, m4 = e & 31;
            *(float4*)&As[0][kk][m4 * 4] = *(const float4*)&Ab[(long)kk * as_k + (m0 + m4 * 4)];
        }
    } else {
        for (int e = tid; e < 2048; e += 256) {
            int mm = e >> 4, kk = e & 15;
            int gm = m0 + mm;
            As[0][kk][mm] = (gm < M) ? Ab[(long)gm * as_m + kk] : 0.f;
        }
    }
    for (int e = tid; e < 512; e += 256) {
        int kk = e >> 5, n4 = e & 31;
        *(float4*)&Xs[0][kk][n4 * 4] = *(const float4*)&Xb[(long)kk * NPTS + n0 + n4 * 4];
    }
    __syncthreads();

    for (int kc = 0; kc < nk; kc++) {
        int cur = kc & 1, nxt = cur ^ 1;
        int k1 = (kc + 1) << 4;
        bool have = (kc + 1) < nk;

        // register prefetch of next chunk (X always; A when col-major)
        float4 px[2], pa[2];
        if (have) {
#pragma unroll
            for (int r = 0; r < 2; r++) {
                int e = tid + r * 256;
                int kk = e >> 5, n4 = e & 31;
                px[r] = *(const float4*)&Xb[(long)(k1 + kk) * NPTS + n0 + n4 * 4];
            }
            if (a_colmajor) {
#pragma unroll
                for (int r = 0; r < 2; r++) {
                    int e = tid + r * 256;
                    int kk = e >> 5, m4 = e & 31;
                    pa[r] = *(const float4*)&Ab[(long)(k1 + kk) * as_k + (m0 + m4 * 4)];
                }
            }
        }

#pragma unroll
        for (int kk = 0; kk < 16; kk++) {
            float a[8];
            *(float4*)a       = *(float4*)&As[cur][kk][ty * 8];
            *(float4*)(a + 4) = *(float4*)&As[cur][kk][ty * 8 + 4];
            u64 xv[4];
#pragma unroll
            for (int j = 0; j < 4; j++) xv[j] = *(u64*)&Xs[cur][kk][tx * 8 + j * 2];
#pragma unroll
            for (int i = 0; i < 8; i++) {
                u64 ai = splat2(a[i]);
#pragma unroll
                for (int j = 0; j < 4; j++) fma2(acc[i][j], ai, xv[j]);
            }
        }
        __syncthreads();

        if (have) {
#pragma unroll
            for (int r = 0; r < 2; r++) {
                int e = tid + r * 256;
                int kk = e >> 5, n4 = e & 31;
                *(float4*)&Xs[nxt][kk][n4 * 4] = px[r];
            }
            if (a_colmajor) {
#pragma unroll
                for (int r = 0; r < 2; r++) {
                    int e = tid + r * 256;
                    int kk = e >> 5, m4 = e & 31;
                    *(float4*)&As[nxt][kk][m4 * 4] = pa[r];
                }
            } else {
                for (int e = tid; e < 2048; e += 256) {
                    int mm = e >> 4, kk = e & 15;
                    int gm = m0 + mm;
                    As[nxt][kk][mm] = (gm < M) ? Ab[(long)gm * as_m + (k1 + kk)] : 0.f;
                }
            }
            __syncthreads();
        }
    }

    if (ypart) {  // fused global max-pool across this N-tile
        float* red = &As[0][0][0];
#pragma unroll
        for (int i = 0; i < 8; i++) {
            int gm = m0 + ty * 8 + i;
            int gmc = gm < M ? gm : 0;
            float mloc = -FINF;
#pragma unroll
            for (int j = 0; j < 4; j++) {
                float lo, hi;
                unpack2(acc[i][j], lo, hi);
                lo = gemm_post(lo, gmc, b, M, addrow, s, o, act, negate);
                hi = gemm_post(hi, gmc, b, M, addrow, s, o, act, negate);
                mloc = fmaxf(mloc, fmaxf(lo, hi));
            }
            red[(ty * 8 + i) * 16 + tx] = mloc;
        }
        __syncthreads();
        if (tid < 128) {
            float m = -FINF;
            for (int q = 0; q < 16; q++) m = fmaxf(m, red[tid * 16 + q]);
            int gm = m0 + tid;
            if (gm < M) ypart[((long)(b * M + gm)) * gridDim.x + blockIdx.x] = m;
        }
    } else {
#pragma unroll
        for (int i = 0; i < 8; i++) {
            int gm = m0 + ty * 8 + i;
            if (gm >= M) continue;
            float out8[8];
#pragma unroll
            for (int j = 0; j < 4; j++) {
                float lo, hi;
                unpack2(acc[i][j], lo, hi);
                out8[j * 2]     = gemm_post(lo, gm, b, M, addrow, s, o, act, negate);
                out8[j * 2 + 1] = gemm_post(hi, gm, b, M, addrow, s, o, act, negate);
            }
            float* dst = Y + (long)b * y_bs + (long)gm * NPTS + n0 + tx * 8;
            *(float4*)dst       = *(float4*)out8;
            *(float4*)(dst + 4) = *(float4*)(out8 + 4);
        }
    }
}

// ---------------- small-case GEMM (K=6 or M=13): 64x64 tile ----------------
#define BM 64
#define BN 64
#define BK 16

__global__ void k_gemm(const float* __restrict__ A, long a_bs, int as_m, long as_k, int a_colmajor,
                       const float* __restrict__ X, long x_bs,
                       float* __restrict__ Y, long y_bs,
                       int M, int K,
                       const float* __restrict__ addrow,
                       const float* __restrict__ s, const float* __restrict__ o,
                       int act, int negate) {
    __shared__ float As[BK][BM + 4];
    __shared__ float Xs[BK][BN + 4];
    int b = blockIdx.z;
    int m0 = blockIdx.y * BM, n0 = blockIdx.x * BN;
    const float* Ab = A + (long)b * a_bs;
    const float* Xb = X + (long)b * x_bs;
    int tid = threadIdx.x;
    int ty = tid >> 4, tx = tid & 15;
    float acc[4][4] = {};
    for (int k0 = 0; k0 < K; k0 += BK) {
        for (int e = tid; e < BK * BM; e += 256) {
            int mm = e >> 4, kk = e & 15;
            int gm = m0 + mm, gk = k0 + kk;
            As[kk][mm] = (gk < K && gm < M) ? Ab[(long)gm * as_m + (long)gk * as_k] : 0.f;
        }
        for (int e = tid; e < BK * BN; e += 256) {
            int kk = e >> 6, nn = e & 63;
            int gk = k0 + kk;
            Xs[kk][nn] = (gk < K) ? Xb[(long)gk * NPTS + n0 + nn] : 0.f;
        }
        __syncthreads();
#pragma unroll
        for (int kk = 0; kk < BK; kk++) {
            float a[4], xv[4];
#pragma unroll
            for (int i = 0; i < 4; i++) a[i] = As[kk][ty * 4 + i];
#pragma unroll
            for (int j = 0; j < 4; j++) xv[j] = Xs[kk][tx * 4 + j];
#pragma unroll
            for (int i = 0; i < 4; i++)
#pragma unroll
                for (int j = 0; j < 4; j++)
                    acc[i][j] = fmaf(a[i], xv[j], acc[i][j]);
        }
        __syncthreads();
    }
#pragma unroll
    for (int i = 0; i < 4; i++) {
        int gm = m0 + ty * 4 + i;
        if (gm >= M) continue;
#pragma unroll
        for (int j = 0; j < 4; j++) {
            float v = gemm_post(acc[i][j], gm, b, M, addrow, s, o, act, negate);
            Y[(long)b * y_bs + (long)gm * NPTS + n0 + tx * 4 + j] = v;
        }
    }
}

// ---------------- edge-conv 2nd half: gather (point-major) + GEMM + max ----
#define H0S 164   // padded col stride (160 cols)

__global__ void k_edge2(const float* __restrict__ w1,
                        const float* __restrict__ s0, const float* __restrict__ o0,
                        const float* __restrict__ s1, const float* __restrict__ o1,
                        int outrow) {
    extern __shared__ float sm[];
    float* w1s = sm;                  // 64*64   [o][c]
    float* h0s = w1s + 4096;          // 64*H0S  [c][col] -> overwritten by H1 [o][col]
    float* vcs = h0s + 64 * H0S;      // 8*64    [p][c] center V values
    float* s0s = vcs + 512;
    float* o0s = s0s + 64;
    float* s1s = o0s + 64;
    float* o1s = s1s + 64;
    int*   idxs = (int*)(o1s + 64);   // 160

    int tid = threadIdx.x;
    int b = blockIdx.y;
    int n0 = blockIdx.x * 8;
    const float* uvt = g_uvt + (long)b * NPTS * 128;

    for (int e = tid; e < 4096; e += 256) w1s[e] = w1[e];
    if (tid < 64) { s0s[tid] = s0[tid]; o0s[tid] = o0[tid]; s1s[tid] = s1[tid]; o1s[tid] = o1[tid]; }
    for (int e = tid; e < 160; e += 256)
        idxs[e] = g_idx[(b * NPTS + n0 + e / 20) * KNN + e % 20];
    if (tid < 128) {
        int p = tid >> 4, cq = tid & 15;
        *(((float4*)vcs) + tid) = *(const float4*)&uvt[(long)(n0 + p) * 128 + 64 + cq * 4];
    }
    __syncthreads();

    for (int e = tid; e < 16 * 160; e += 256) {
        int cq = e / 160, col = e - cq * 160;
        int p = col / 20;
        int j = idxs[col];
        float4 u = *(const float4*)&uvt[(long)j * 128 + cq * 4];
        float4 vv = *(((const float4*)vcs) + p * 16 + cq);
        int c = cq * 4;
        h0s[(c + 0) * H0S + col] = lrelu(fmaf(u.x + vv.x, s0s[c + 0], o0s[c + 0]));
        h0s[(c + 1) * H0S + col] = lrelu(fmaf(u.y + vv.y, s0s[c + 1], o0s[c + 1]));
        h0s[(c + 2) * H0S + col] = lrelu(fmaf(u.z + vv.z, s0s[c + 2], o0s[c + 2]));
        h0s[(c + 3) * H0S + col] = lrelu(fmaf(u.w + vv.w, s0s[c + 3], o0s[c + 3]));
    }
    __syncthreads();

    int ty = tid >> 4, tx = tid & 15;
    for (int iter = 0; iter < 3; iter++) {
        int g = tx + iter * 16;
        float acc[4][4] = {};
        if (g < 40) {
#pragma unroll
            for (int c4 = 0; c4 < 16; c4++) {
                float4 h[4], w[4];
#pragma unroll
                for (int q = 0; q < 4; q++) h[q] = *(const float4*)&h0s[(c4 * 4 + q) * H0S + g * 4];
#pragma unroll
                for (int q = 0; q < 4; q++) w[q] = *(const float4*)&w1s[(ty * 4 + q) * 64 + c4 * 4];
#pragma unroll
                for (int i = 0; i < 4; i++) {
                    acc[i][0] = fmaf(w[i].x, h[0].x, acc[i][0]);
                    acc[i][0] = fmaf(w[i].y, h[1].x, acc[i][0]);
                    acc[i][0] = fmaf(w[i].z, h[2].x, acc[i][0]);
                    acc[i][0] = fmaf(w[i].w, h[3].x, acc[i][0]);
                    acc[i][1] = fmaf(w[i].x, h[0].y, acc[i][1]);
                    acc[i][1] = fmaf(w[i].y, h[1].y, acc[i][1]);
                    acc[i][1] = fmaf(w[i].z, h[2].y, acc[i][1]);
                    acc[i][1] = fmaf(w[i].w, h[3].y, acc[i][1]);
                    acc[i][2] = fmaf(w[i].x, h[0].z, acc[i][2]);
                    acc[i][2] = fmaf(w[i].y, h[1].z, acc[i][2]);
                    acc[i][2] = fmaf(w[i].z, h[2].z, acc[i][2]);
                    acc[i][2] = fmaf(w[i].w, h[3].z, acc[i][2]);
                    acc[i][3] = fmaf(w[i].x, h[0].w, acc[i][3]);
                    acc[i][3] = fmaf(w[i].y, h[1].w, acc[i][3]);
                    acc[i][3] = fmaf(w[i].z, h[2].w, acc[i][3]);
                    acc[i][3] = fmaf(w[i].w, h[3].w, acc[i][3]);
                }
            }
        }
        __syncthreads();
        if (g < 40) {
#pragma unroll
            for (int i = 0; i < 4; i++)
#pragma unroll
                for (int j = 0; j < 4; j++)
                    h0s[(ty * 4 + i) * H0S + g * 4 + j] = acc[i][j];
        }
        __syncthreads();
    }

    for (int e = tid; e < 512; e += 256) {
        int o = e >> 3, p = e & 7;
        float ss = s1s[o], oo = o1s[o];
        float m = -FINF;
#pragma unroll
        for (int kk = 0; kk < KNN; kk++) {
            float v = lrelu(fmaf(h0s[o * H0S + p * 20 + kk], ss, oo));
            m = fmaxf(m, v);
        }
        g_xc[((long)(b * 192 + outrow + o)) * NPTS + n0 + p] = m;
    }
}

// ---------------- small reductions ----------------
__global__ void k_gred(int width) {
    int e = blockIdx.x * 256 + threadIdx.x;
    if (e >= BATCH * 1024) return;
    const float* p = g_gpart + (long)e * width;
    float m = -FINF;
    for (int t = 0; t < width; t++) m = fmaxf(m, p[t]);
    g_g[e] = m;
}

__global__ void k_gterm(const float* __restrict__ wf1) {
    int e = blockIdx.x * 256 + threadIdx.x;
    if (e >= BATCH * 512) return;
    int b = e / 512, mo = e - b * 512;
    const float* w = wf1 + (long)mo * 1216 + 192;
    const float* gg = g_g + b * 1024;
    float acc = 0.f;
    for (int c = 0; c < 1024; c++) acc = fmaf(w[c], gg[c], acc);
    g_gterm[e] = acc;
}

// ---------------- host orchestration ----------------
#define EDGE2_SMEM ((4096 + 64 * H0S + 512 + 4 * 64) * 4 + 160 * 4)
#define SIM_TILES (32 * 33 / 2)
#define MIR_TILES (32 * 31 / 2)

extern "C" void kernel_launch(void* const* d_in, const int* in_sizes, int n_in,
                              void* d_out, int out_size) {
    const float* x    = (const float*)d_in[0];
    const float* w1_0 = (const float*)d_in[1];
    const float* s1_0 = (const float*)d_in[2];
    const float* o1_0 = (const float*)d_in[3];
    const float* w1_1 = (const float*)d_in[4];
    const float* s1_1 = (const float*)d_in[5];
    const float* o1_1 = (const float*)d_in[6];
    const float* w2_0 = (const float*)d_in[7];
    const float* s2_0 = (const float*)d_in[8];
    const float* o2_0 = (const float*)d_in[9];
    const float* w2_1 = (const float*)d_in[10];
    const float* s2_1 = (const float*)d_in[11];
    const float* o2_1 = (const float*)d_in[12];
    const float* w3_0 = (const float*)d_in[13];
    const float* s3_0 = (const float*)d_in[14];
    const float* o3_0 = (const float*)d_in[15];
    const float* w3_1 = (const float*)d_in[16];
    const float* s3_1 = (const float*)d_in[17];
    const float* o3_1 = (const float*)d_in[18];
    const float* w4   = (const float*)d_in[19];
    const float* b4   = (const float*)d_in[20];
    const float* wf1  = (const float*)d_in[21];
    const float* sf1  = (const float*)d_in[22];
    const float* of1  = (const float*)d_in[23];
    const float* wf2  = (const float*)d_in[24];
    const float* sf2  = (const float*)d_in[25];
    const float* of2  = (const float*)d_in[26];
    const float* wf3  = (const float*)d_in[27];
    float* out = (float*)d_out;
    (void)in_sizes; (void)n_in; (void)out_size;

    float *p_xc, *p_xn, *p_uv, *p_w2, *p_gterm, *p_h1, *p_h2, *p_gpart, *p_dmat;
    cudaGetSymbolAddress((void**)&p_dmat,  g_dmat);
    cudaGetSymbolAddress((void**)&p_xc,    g_xc);
    cudaGetSymbolAddress((void**)&p_xn,    g_xn);
    cudaGetSymbolAddress((void**)&p_uv,    g_uv);
    cudaGetSymbolAddress((void**)&p_w2,    g_w2);
    cudaGetSymbolAddress((void**)&p_gpart, g_gpart);
    cudaGetSymbolAddress((void**)&p_gterm, g_gterm);
    cudaGetSymbolAddress((void**)&p_h1,    g_h1);
    cudaGetSymbolAddress((void**)&p_h2,    g_h2);

    cudaFuncSetAttribute(k_edge2, cudaFuncAttributeMaxDynamicSharedMemorySize, EDGE2_SMEM);

    dim3 knnG(NPTS / 8, BATCH);
    dim3 edgeG(NPTS / 8, BATCH);
    dim3 uvtG(4, 128, BATCH);
    dim3 simG(SIM_TILES, 1, BATCH);
    dim3 mirG(MIR_TILES, 1, BATCH);

    // ---- block 1: knn_euclid(x) + edge_conv1 -> xc[0:64) ----
    k_knn_euclid<<<knnG, 256>>>(x);
    k_w2prep<<<3, 256>>>(w1_0, 6);
    k_gemm<<<dim3(64, 2, BATCH), 256>>>(p_w2, 0, 6, 1, 0, x, (long)6 * NPTS,
                                        p_uv, (long)128 * NPTS, 128, 6,
                                        nullptr, nullptr, nullptr, 0, 0);
    k_uvt<<<uvtG, 256>>>();
    k_edge2<<<edgeG, 256, EDGE2_SMEM>>>(w1_1, s1_0, o1_0, s1_1, o1_1, 0);

    // ---- block 2: knn_cosine(x1) sym-GEMM + mirror + edge_conv2 ----
    k_normalize<<<dim3(16, BATCH), 256>>>(0);
    k_gemm_big<<<simG, 256>>>(p_xn, (long)64 * NPTS, 1, NPTS, 1,
                              p_xn, (long)64 * NPTS,
                              p_dmat, (long)NPTS * NPTS, NPTS, 64,
                              nullptr, nullptr, nullptr, 0, 1, nullptr, 1);
    k_mirror<<<mirG, 256>>>();
    k_topk_dmat<<<knnG, 256>>>();
    k_w2prep<<<32, 256>>>(w2_0, 64);
    k_gemm_big<<<dim3(32, 1, BATCH), 256>>>(p_w2, 0, 64, 0, 0, p_xc, (long)192 * NPTS,
                                            p_uv, (long)128 * NPTS, 128, 64,
                                            nullptr, nullptr, nullptr, 0, 0, nullptr, 0);
    k_uvt<<<uvtG, 256>>>();
    k_edge2<<<edgeG, 256, EDGE2_SMEM>>>(w2_1, s2_0, o2_0, s2_1, o2_1, 64);

    // ---- block 3: knn_cosine(x2) sym-GEMM + mirror + edge_conv3 ----
    k_normalize<<<dim3(16, BATCH), 256>>>(64);
    k_gemm_big<<<simG, 256>>>(p_xn, (long)64 * NPTS, 1, NPTS, 1,
                              p_xn, (long)64 * NPTS,
                              p_dmat, (long)NPTS * NPTS, NPTS, 64,
                              nullptr, nullptr, nullptr, 0, 1, nullptr, 1);
    k_mirror<<<mirG, 256>>>();
    k_topk_dmat<<<knnG, 256>>>();
    k_w2prep<<<32, 256>>>(w3_0, 64);
    k_gemm_big<<<dim3(32, 1, BATCH), 256>>>(p_w2, 0, 64, 0, 0, p_xc + (long)64 * NPTS, (long)192 * NPTS,
                                            p_uv, (long)128 * NPTS, 128, 64,
                                            nullptr, nullptr, nullptr, 0, 0, nullptr, 0);
    k_uvt<<<uvtG, 256>>>();
    k_edge2<<<edgeG, 256, EDGE2_SMEM>>>(w3_1, s3_0, o3_0, s3_1, o3_1, 128);

    // ---- head: w4 + fused global max-pool, gterm, wf1 -> wf2 -> wf3 ----
    k_gemm_big<<<dim3(32, 8, BATCH), 256>>>(w4, 0, 192, 0, 0, p_xc, (long)192 * NPTS,
                                            nullptr, 0, 1024, 192,
                                            nullptr, nullptr, b4, 1, 0, p_gpart, 0);
    k_gred<<<16, 256>>>(32);
    k_gterm<<<8, 256>>>(wf1);
    k_gemm_big<<<dim3(32, 4, BATCH), 256>>>(wf1, 0, 1216, 0, 0, p_xc, (long)192 * NPTS,
                                            p_h1, (long)512 * NPTS, 512, 192,
                                            p_gterm, sf1, of1, 1, 0, nullptr, 0);
    k_gemm_big<<<dim3(32, 2, BATCH), 256>>>(wf2, 0, 512, 0, 0, p_h1, (long)512 * NPTS,
                                            p_h2, (long)256 * NPTS, 256, 512,
                                            nullptr, sf2, of2, 1, 0, nullptr, 0);
    k_gemm<<<dim3(64, 1, BATCH), 256>>>(wf3, 0, 256, 1, 0, p_h2, (long)256 * NPTS,
                                        out, (long)13 * NPTS, 13, 256,
                                        nullptr, nullptr, nullptr, 0, 0);
}

// round 15
// speedup vs baseline: 1.2319x; 1.0228x over previous
#include <cuda_runtime.h>
#include <math.h>
#include <stdint.h>

#define BATCH 4
#define NPTS  4096
#define KNN   20
#define FINF  __int_as_float(0x7f800000)
#define FULLM 0xffffffffu
#define U64MAX 0xffffffffffffffffull

typedef unsigned long long u64;

// ---------------- scratch (device globals; no allocations allowed) ----------
__device__ float g_dmat[BATCH * NPTS * NPTS];    // -sim for cosine knn (268MB)
__device__ int   g_idx [BATCH * NPTS * KNN];
__device__ float g_xc  [BATCH * 192 * NPTS];     // concat x1|x2|x3
__device__ float g_xn  [BATCH * 64 * NPTS];      // normalized feats
__device__ float g_uv  [BATCH * 128 * NPTS];     // U rows 0-63, V rows 64-127 (ch-major)
__device__ float g_uvt [BATCH * NPTS * 128];     // point-major copy: uvt[n][c]
__device__ float g_w2  [128 * 64];               // [w0a ; w0b-w0a]
__device__ float g_gpart[BATCH * 1024 * 64];
__device__ float g_g   [BATCH * 1024];
__device__ float g_gterm[BATCH * 512];
__device__ float g_h1  [BATCH * 512 * NPTS];
__device__ float g_h2  [BATCH * 256 * NPTS];

__device__ __forceinline__ float lrelu(float v) { return v >= 0.f ? v : 0.2f * v; }

__device__ __forceinline__ u64 splat2(float a) {
    u64 r;
    unsigned int ai = __float_as_uint(a);
    asm("mov.b64 %0, {%1, %1};" : "=l"(r) : "r"(ai));
    return r;
}
__device__ __forceinline__ void fma2(u64& d, u64 a, u64 b) {
    asm("fma.rn.f32x2 %0, %1, %2, %0;" : "+l"(d) : "l"(a), "l"(b));
}
__device__ __forceinline__ void unpack2(u64 v, float& lo, float& hi) {
    unsigned int l, h;
    asm("mov.b64 {%0, %1}, %2;" : "=r"(l), "=r"(h) : "l"(v));
    lo = __uint_as_float(l); hi = __uint_as_float(h);
}

// ---------------- u64 key top-k machinery ----------------
__device__ __forceinline__ u64 fkey(float d, int j) {
    unsigned int u = __float_as_uint(d);
    u = (u & 0x80000000u) ? ~u : (u | 0x80000000u);
    return ((u64)u << 32) | (unsigned int)j;
}

#define INS5(key) do {                                              \
    u64 _k = (key);                                                 \
    if (_k < c4) {                                                  \
        if (_k < c3) { c4 = c3;                                     \
            if (_k < c2) { c3 = c2;                                 \
                if (_k < c1) { c2 = c1;                             \
                    if (_k < c0) { c1 = c0; c0 = _k; } else c1 = _k;\
                } else c2 = _k;                                     \
            } else c3 = _k;                                         \
        } else c4 = _k;                                             \
    }                                                               \
} while (0)

__device__ __forceinline__ u64 warp_min_u64(u64 v) {
#pragma unroll
    for (int off = 16; off > 0; off >>= 1) {
        u64 o = __shfl_xor_sync(FULLM, v, off);
        v = (o < v) ? o : v;
    }
    return v;
}

__device__ __forceinline__ u64 tk5_merge(u64& c0, u64& c1, u64& c2, u64& c3, u64& c4,
                                         int lane, int* outrow, bool& need2) {
    int pops = 0;
    u64 w = 0;
#pragma unroll 1
    for (int r = 0; r < KNN; r++) {
        w = warp_min_u64(c0);
        if (c0 == w) { c0 = c1; c1 = c2; c2 = c3; c3 = c4; c4 = U64MAX; pops++; }
        if (lane == 0) outrow[r] = (int)(w & 0xffffffffu);
    }
    need2 = __any_sync(FULLM, pops >= 5);
    return w;
}

__device__ __forceinline__ void tk_select_buf(const u64* buf, int m, int lane, int* outrow) {
    u64 k0 = (lane < m) ? buf[lane] : U64MAX;
    u64 k1 = (32 + lane < m) ? buf[32 + lane] : U64MAX;
#pragma unroll 1
    for (int r = 0; r < KNN; r++) {
        u64 lm = (k0 < k1) ? k0 : k1;
        u64 w = warp_min_u64(lm);
        if (k0 == w) k0 = U64MAX;
        else if (k1 == w) k1 = U64MAX;
        if (lane == 0) outrow[r] = (int)(w & 0xffffffffu);
    }
}

// ---------------- kNN euclid (C=6, warp per query) ----------------
__global__ __launch_bounds__(256)
void k_knn_euclid(const float* __restrict__ x) {
    __shared__ u64 sbuf[8][64];
    int b = blockIdx.y;
    int warp = threadIdx.x >> 5, lane = threadIdx.x & 31;
    int i = blockIdx.x * 8 + warp;
    const float* xb = x + b * 6 * NPTS;
    float xi[6];
#pragma unroll
    for (int c = 0; c < 6; c++) xi[c] = xb[c * NPTS + i];
    float sqi = 0.f;
#pragma unroll
    for (int c = 0; c < 6; c++) sqi = fmaf(xi[c], xi[c], sqi);

    u64 c0 = U64MAX, c1 = U64MAX, c2 = U64MAX, c3 = U64MAX, c4 = U64MAX;
    for (int tblk = 0; tblk < NPTS; tblk += 128) {
        int j0 = tblk + lane * 4;
        float4 row[6];
#pragma unroll
        for (int c = 0; c < 6; c++) row[c] = *(const float4*)&xb[c * NPTS + j0];
        float d0 = sqi, d1 = sqi, d2 = sqi, d3 = sqi;
#pragma unroll
        for (int c = 0; c < 6; c++) {
            d0 = fmaf(row[c].x - 2.f * xi[c], row[c].x, d0);
            d1 = fmaf(row[c].y - 2.f * xi[c], row[c].y, d1);
            d2 = fmaf(row[c].z - 2.f * xi[c], row[c].z, d2);
            d3 = fmaf(row[c].w - 2.f * xi[c], row[c].w, d3);
        }
        INS5(fkey(d0, j0));
        INS5(fkey(d1, j0 + 1));
        INS5(fkey(d2, j0 + 2));
        INS5(fkey(d3, j0 + 3));
    }
    int* outrow = g_idx + (b * NPTS + i) * KNN;
    bool need2;
    u64 Tp = tk5_merge(c0, c1, c2, c3, c4, lane, outrow, need2);

    if (need2) {
        u64* buf = sbuf[warp];
        int base = 0;
        for (int tblk = 0; tblk < NPTS; tblk += 128) {
            int j0 = tblk + lane * 4;
            float4 row[6];
#pragma unroll
            for (int c = 0; c < 6; c++) row[c] = *(const float4*)&xb[c * NPTS + j0];
            float dd[4] = {sqi, sqi, sqi, sqi};
#pragma unroll
            for (int c = 0; c < 6; c++) {
                dd[0] = fmaf(row[c].x - 2.f * xi[c], row[c].x, dd[0]);
                dd[1] = fmaf(row[c].y - 2.f * xi[c], row[c].y, dd[1]);
                dd[2] = fmaf(row[c].z - 2.f * xi[c], row[c].z, dd[2]);
                dd[3] = fmaf(row[c].w - 2.f * xi[c], row[c].w, dd[3]);
            }
#pragma unroll
            for (int q = 0; q < 4; q++) {
                u64 k = fkey(dd[q], j0 + q);
                bool p = (k <= Tp);
                unsigned m = __ballot_sync(FULLM, p);
                int pos = base + __popc(m & ((1u << lane) - 1u));
                if (p && pos < 64) buf[pos] = k;
                base += __popc(m);
            }
        }
        __syncwarp();
        tk_select_buf(buf, base < 64 ? base : 64, lane, outrow);
    }
}

// ---------------- top-k from materialized (-sim) matrix (warp per row) ------
__global__ __launch_bounds__(256)
void k_topk_dmat() {
    __shared__ u64 sbuf[8][64];
    int b = blockIdx.y;
    int warp = threadIdx.x >> 5, lane = threadIdx.x & 31;
    int i = blockIdx.x * 8 + warp;
    const float* row = g_dmat + ((long)(b * NPTS + i)) * NPTS;

    u64 c0 = U64MAX, c1 = U64MAX, c2 = U64MAX, c3 = U64MAX, c4 = U64MAX;
    for (int tblk = 0; tblk < NPTS; tblk += 128) {
        int j0 = tblk + lane * 4;
        float4 v = *(const float4*)&row[j0];
        INS5(fkey(v.x, j0));
        INS5(fkey(v.y, j0 + 1));
        INS5(fkey(v.z, j0 + 2));
        INS5(fkey(v.w, j0 + 3));
    }
    int* outrow = g_idx + (b * NPTS + i) * KNN;
    bool need2;
    u64 Tp = tk5_merge(c0, c1, c2, c3, c4, lane, outrow, need2);

    if (need2) {
        u64* buf = sbuf[warp];
        int base = 0;
        for (int tblk = 0; tblk < NPTS; tblk += 128) {
            int j0 = tblk + lane * 4;
            float4 v = *(const float4*)&row[j0];
            u64 kk[4] = {fkey(v.x, j0), fkey(v.y, j0 + 1), fkey(v.z, j0 + 2), fkey(v.w, j0 + 3)};
#pragma unroll
            for (int q = 0; q < 4; q++) {
                bool p = (kk[q] <= Tp);
                unsigned m = __ballot_sync(FULLM, p);
                int pos = base + __popc(m & ((1u << lane) - 1u));
                if (p && pos < 64) buf[pos] = kk[q];
                base += __popc(m);
            }
        }
        __syncwarp();
        tk_select_buf(buf, base < 64 ? base : 64, lane, outrow);
    }
}

// ---------------- channel-wise L2 normalize (64ch) ----------------
__global__ void k_normalize(int srcrow) {
    int b = blockIdx.y;
    int n = blockIdx.x * 256 + threadIdx.x;
    const float* src = g_xc + ((long)b * 192 + srcrow) * NPTS;
    float s = 0.f;
    for (int c = 0; c < 64; c++) { float v = src[c * NPTS + n]; s = fmaf(v, v, s); }
    float inv = 1.f / (sqrtf(s) + 1e-8f);
    float* dst = g_xn + (long)b * 64 * NPTS;
    for (int c = 0; c < 64; c++) dst[c * NPTS + n] = src[c * NPTS + n] * inv;
}

// ---------------- build W2 = [w0a ; w0b - w0a] ----------------
__global__ void k_w2prep(const float* __restrict__ w0, int C) {
    int e = blockIdx.x * 256 + threadIdx.x;
    if (e >= 128 * C) return;
    int o = e / C, c = e % C;
    float val = (o < 64) ? w0[o * (2 * C) + c]
                         : (w0[(o - 64) * (2 * C) + C + c] - w0[(o - 64) * (2 * C) + c]);
    g_w2[o * C + c] = val;
}

// ---------------- transpose g_uv (ch-major) -> g_uvt (point-major) ----------
__global__ void k_uvt() {
    __shared__ float t[32][33];
    int b = blockIdx.z;
    int cb = blockIdx.x * 32, nb = blockIdx.y * 32;
    int tx = threadIdx.x & 31, ty = threadIdx.x >> 5;  // ty 0..7
    const float* src = g_uv + (long)b * 128 * NPTS;
    float* dst = g_uvt + (long)b * NPTS * 128;
#pragma unroll
    for (int k = 0; k < 4; k++)
        t[ty + 8 * k][tx] = src[(long)(cb + ty + 8 * k) * NPTS + nb + tx];
    __syncthreads();
#pragma unroll
    for (int k = 0; k < 4; k++)
        dst[(long)(nb + ty + 8 * k) * 128 + cb + tx] = t[tx][ty + 8 * k];
}

// ---------------- post-op ----------------
__device__ __forceinline__ float gemm_post(float v, int gm, int b, int M,
                                           const float* addrow, const float* s,
                                           const float* o, int act, int negate) {
    if (addrow) v += addrow[b * M + gm];
    if (s) v *= s[gm];
    if (o) v += o[gm];
    if (act) v = lrelu(v);
    if (negate) v = -v;
    return v;
}

// ---------------- big GEMM: 128x128 tile, 8x8/thread, fma.f32x2 -------------
// Double-buffered smem; X (and col-major A) prefetched into registers.
// sym=1: grid.x = T*(T+1)/2 upper-triangle tiles (bx >= by); off-diagonal
// tiles ALSO write their transpose via per-thread register transpose
// (negate applied; only valid for the plain-negate sim use).
__global__ __launch_bounds__(256, 2)
void k_gemm_big(const float* __restrict__ A, long a_bs, int as_m, long as_k, int a_colmajor,
                const float* __restrict__ X, long x_bs,
                float* __restrict__ Y, long y_bs,
                int M, int K,
                const float* __restrict__ addrow,
                const float* __restrict__ s, const float* __restrict__ o,
                int act, int negate,
                float* __restrict__ ypart, int sym) {
    __shared__ float As[2][16][128];
    __shared__ float Xs[2][16][128];
    int b = blockIdx.z;
    int bx = blockIdx.x, by = blockIdx.y;
    if (sym) {
        int id = blockIdx.x;
        int r = (int)((sqrtf(8.f * id + 1.f) - 1.f) * 0.5f);
        while ((r + 1) * (r + 2) / 2 <= id) r++;
        while (r * (r + 1) / 2 > id) r--;
        bx = r; by = id - r * (r + 1) / 2;   // bx >= by
    }
    int m0 = by * 128, n0 = bx * 128;
    const float* Ab = A + (long)b * a_bs;
    const float* Xb = X + (long)b * x_bs;
    int tid = threadIdx.x;
    int ty = tid >> 4, tx = tid & 15;

    u64 acc[8][4];
#pragma unroll
    for (int i = 0; i < 8; i++)
#pragma unroll
        for (int j = 0; j < 4; j++) acc[i][j] = 0ull;

    int nk = K >> 4;

    // prologue: chunk 0 straight to smem buffer 0
    if (a_colmajor) {
        for (int e = tid; e < 512; e += 256) {
            int kk = e >> 5, m4 = e & 31;
            *(float4*)&As[0][kk][m4 * 4] = *(const float4*)&Ab[(long)kk * as_k + (m0 + m4 * 4)];
        }
    } else {
        for (int e = tid; e < 2048; e += 256) {
            int mm = e >> 4, kk = e & 15;
            int gm = m0 + mm;
            As[0][kk][mm] = (gm < M) ? Ab[(long)gm * as_m + kk] : 0.f;
        }
    }
    for (int e = tid; e < 512; e += 256) {
        int kk = e >> 5, n4 = e & 31;
        *(float4*)&Xs[0][kk][n4 * 4] = *(const float4*)&Xb[(long)kk * NPTS + n0 + n4 * 4];
    }
    __syncthreads();

    for (int kc = 0; kc < nk; kc++) {
        int cur = kc & 1, nxt = cur ^ 1;
        int k1 = (kc + 1) << 4;
        bool have = (kc + 1) < nk;

        float4 px[2], pa[2];
        if (have) {
#pragma unroll
            for (int r = 0; r < 2; r++) {
                int e = tid + r * 256;
                int kk = e >> 5, n4 = e & 31;
                px[r] = *(const float4*)&Xb[(long)(k1 + kk) * NPTS + n0 + n4 * 4];
            }
            if (a_colmajor) {
#pragma unroll
                for (int r = 0; r < 2; r++) {
                    int e = tid + r * 256;
                    int kk = e >> 5, m4 = e & 31;
                    pa[r] = *(const float4*)&Ab[(long)(k1 + kk) * as_k + (m0 + m4 * 4)];
                }
            }
        }

#pragma unroll
        for (int kk = 0; kk < 16; kk++) {
            float a[8];
            *(float4*)a       = *(float4*)&As[cur][kk][ty * 8];
            *(float4*)(a + 4) = *(float4*)&As[cur][kk][ty * 8 + 4];
            u64 xv[4];
#pragma unroll
            for (int j = 0; j < 4; j++) xv[j] = *(u64*)&Xs[cur][kk][tx * 8 + j * 2];
#pragma unroll
            for (int i = 0; i < 8; i++) {
                u64 ai = splat2(a[i]);
#pragma unroll
                for (int j = 0; j < 4; j++) fma2(acc[i][j], ai, xv[j]);
            }
        }
        __syncthreads();

        if (have) {
#pragma unroll
            for (int r = 0; r < 2; r++) {
                int e = tid + r * 256;
                int kk = e >> 5, n4 = e & 31;
                *(float4*)&Xs[nxt][kk][n4 * 4] = px[r];
            }
            if (a_colmajor) {
#pragma unroll
                for (int r = 0; r < 2; r++) {
                    int e = tid + r * 256;
                    int kk = e >> 5, m4 = e & 31;
                    *(float4*)&As[nxt][kk][m4 * 4] = pa[r];
                }
            } else {
                for (int e = tid; e < 2048; e += 256) {
                    int mm = e >> 4, kk = e & 15;
                    int gm = m0 + mm;
                    As[nxt][kk][mm] = (gm < M) ? Ab[(long)gm * as_m + (k1 + kk)] : 0.f;
                }
            }
            __syncthreads();
        }
    }

    if (ypart) {  // fused global max-pool across this N-tile
        float* red = &As[0][0][0];
#pragma unroll
        for (int i = 0; i < 8; i++) {
            int gm = m0 + ty * 8 + i;
            int gmc = gm < M ? gm : 0;
            float mloc = -FINF;
#pragma unroll
            for (int j = 0; j < 4; j++) {
                float lo, hi;
                unpack2(acc[i][j], lo, hi);
                lo = gemm_post(lo, gmc, b, M, addrow, s, o, act, negate);
                hi = gemm_post(hi, gmc, b, M, addrow, s, o, act, negate);
                mloc = fmaxf(mloc, fmaxf(lo, hi));
            }
            red[(ty * 8 + i) * 16 + tx] = mloc;
        }
        __syncthreads();
        if (tid < 128) {
            float m = -FINF;
            for (int q = 0; q < 16; q++) m = fmaxf(m, red[tid * 16 + q]);
            int gm = m0 + tid;
            if (gm < M) ypart[((long)(b * M + gm)) * gridDim.x + blockIdx.x] = m;
        }
    } else {
#pragma unroll
        for (int i = 0; i < 8; i++) {
            int gm = m0 + ty * 8 + i;
            if (gm >= M) continue;
            float out8[8];
#pragma unroll
            for (int j = 0; j < 4; j++) {
                float lo, hi;
                unpack2(acc[i][j], lo, hi);
                out8[j * 2]     = gemm_post(lo, gm, b, M, addrow, s, o, act, negate);
                out8[j * 2 + 1] = gemm_post(hi, gm, b, M, addrow, s, o, act, negate);
            }
            float* dst = Y + (long)b * y_bs + (long)gm * NPTS + n0 + tx * 8;
            *(float4*)dst       = *(float4*)out8;
            *(float4*)(dst + 4) = *(float4*)(out8 + 4);
        }
        // symmetric off-diagonal: per-thread register transpose of the 8x8
        // micro-tile; contiguous 32B stores along m. (negate-only post.)
        if (sym && bx != by) {
#pragma unroll
            for (int jj = 0; jj < 8; jj++) {
                float col[8];
#pragma unroll
                for (int i = 0; i < 8; i++) {
                    float lo, hi;
                    unpack2(acc[i][jj >> 1], lo, hi);
                    col[i] = -((jj & 1) ? hi : lo);
                }
                float* dst = Y + (long)b * y_bs + (long)(n0 + tx * 8 + jj) * NPTS + m0 + ty * 8;
                *(float4*)dst       = *(float4*)col;
                *(float4*)(dst + 4) = *(float4*)(col + 4);
            }
        }
    }
}

// ---------------- small-case GEMM (K=6 or M=13): 64x64 tile ----------------
#define BM 64
#define BN 64
#define BK 16

__global__ void k_gemm(const float* __restrict__ A, long a_bs, int as_m, long as_k, int a_colmajor,
                       const float* __restrict__ X, long x_bs,
                       float* __restrict__ Y, long y_bs,
                       int M, int K,
                       const float* __restrict__ addrow,
                       const float* __restrict__ s, const float* __restrict__ o,
                       int act, int negate) {
    __shared__ float As[BK][BM + 4];
    __shared__ float Xs[BK][BN + 4];
    int b = blockIdx.z;
    int m0 = blockIdx.y * BM, n0 = blockIdx.x * BN;
    const float* Ab = A + (long)b * a_bs;
    const float* Xb = X + (long)b * x_bs;
    int tid = threadIdx.x;
    int ty = tid >> 4, tx = tid & 15;
    float acc[4][4] = {};
    for (int k0 = 0; k0 < K; k0 += BK) {
        for (int e = tid; e < BK * BM; e += 256) {
            int mm = e >> 4, kk = e & 15;
            int gm = m0 + mm, gk = k0 + kk;
            As[kk][mm] = (gk < K && gm < M) ? Ab[(long)gm * as_m + (long)gk * as_k] : 0.f;
        }
        for (int e = tid; e < BK * BN; e += 256) {
            int kk = e >> 6, nn = e & 63;
            int gk = k0 + kk;
            Xs[kk][nn] = (gk < K) ? Xb[(long)gk * NPTS + n0 + nn] : 0.f;
        }
        __syncthreads();
#pragma unroll
        for (int kk = 0; kk < BK; kk++) {
            float a[4], xv[4];
#pragma unroll
            for (int i = 0; i < 4; i++) a[i] = As[kk][ty * 4 + i];
#pragma unroll
            for (int j = 0; j < 4; j++) xv[j] = Xs[kk][tx * 4 + j];
#pragma unroll
            for (int i = 0; i < 4; i++)
#pragma unroll
                for (int j = 0; j < 4; j++)
                    acc[i][j] = fmaf(a[i], xv[j], acc[i][j]);
        }
        __syncthreads();
    }
#pragma unroll
    for (int i = 0; i < 4; i++) {
        int gm = m0 + ty * 4 + i;
        if (gm >= M) continue;
#pragma unroll
        for (int j = 0; j < 4; j++) {
            float v = gemm_post(acc[i][j], gm, b, M, addrow, s, o, act, negate);
            Y[(long)b * y_bs + (long)gm * NPTS + n0 + tx * 4 + j] = v;
        }
    }
}

// ---------------- edge-conv 2nd half: gather (point-major) + GEMM + max ----
#define H0S 164   // padded col stride (160 cols)

__global__ void k_edge2(const float* __restrict__ w1,
                        const float* __restrict__ s0, const float* __restrict__ o0,
                        const float* __restrict__ s1, const float* __restrict__ o1,
                        int outrow) {
    extern __shared__ float sm[];
    float* w1s = sm;                  // 64*64   [o][c]
    float* h0s = w1s + 4096;          // 64*H0S  [c][col] -> overwritten by H1 [o][col]
    float* vcs = h0s + 64 * H0S;      // 8*64    [p][c] center V values
    float* s0s = vcs + 512;
    float* o0s = s0s + 64;
    float* s1s = o0s + 64;
    float* o1s = s1s + 64;
    int*   idxs = (int*)(o1s + 64);   // 160

    int tid = threadIdx.x;
    int b = blockIdx.y;
    int n0 = blockIdx.x * 8;
    const float* uvt = g_uvt + (long)b * NPTS * 128;

    for (int e = tid; e < 4096; e += 256) w1s[e] = w1[e];
    if (tid < 64) { s0s[tid] = s0[tid]; o0s[tid] = o0[tid]; s1s[tid] = s1[tid]; o1s[tid] = o1[tid]; }
    for (int e = tid; e < 160; e += 256)
        idxs[e] = g_idx[(b * NPTS + n0 + e / 20) * KNN + e % 20];
    if (tid < 128) {
        int p = tid >> 4, cq = tid & 15;
        *(((float4*)vcs) + tid) = *(const float4*)&uvt[(long)(n0 + p) * 128 + 64 + cq * 4];
    }
    __syncthreads();

    for (int e = tid; e < 16 * 160; e += 256) {
        int cq = e / 160, col = e - cq * 160;
        int p = col / 20;
        int j = idxs[col];
        float4 u = *(const float4*)&uvt[(long)j * 128 + cq * 4];
        float4 vv = *(((const float4*)vcs) + p * 16 + cq);
        int c = cq * 4;
        h0s[(c + 0) * H0S + col] = lrelu(fmaf(u.x + vv.x, s0s[c + 0], o0s[c + 0]));
        h0s[(c + 1) * H0S + col] = lrelu(fmaf(u.y + vv.y, s0s[c + 1], o0s[c + 1]));
        h0s[(c + 2) * H0S + col] = lrelu(fmaf(u.z + vv.z, s0s[c + 2], o0s[c + 2]));
        h0s[(c + 3) * H0S + col] = lrelu(fmaf(u.w + vv.w, s0s[c + 3], o0s[c + 3]));
    }
    __syncthreads();

    int ty = tid >> 4, tx = tid & 15;
    for (int iter = 0; iter < 3; iter++) {
        int g = tx + iter * 16;
        float acc[4][4] = {};
        if (g < 40) {
#pragma unroll
            for (int c4 = 0; c4 < 16; c4++) {
                float4 h[4], w[4];
#pragma unroll
                for (int q = 0; q < 4; q++) h[q] = *(const float4*)&h0s[(c4 * 4 + q) * H0S + g * 4];
#pragma unroll
                for (int q = 0; q < 4; q++) w[q] = *(const float4*)&w1s[(ty * 4 + q) * 64 + c4 * 4];
#pragma unroll
                for (int i = 0; i < 4; i++) {
                    acc[i][0] = fmaf(w[i].x, h[0].x, acc[i][0]);
                    acc[i][0] = fmaf(w[i].y, h[1].x, acc[i][0]);
                    acc[i][0] = fmaf(w[i].z, h[2].x, acc[i][0]);
                    acc[i][0] = fmaf(w[i].w, h[3].x, acc[i][0]);
                    acc[i][1] = fmaf(w[i].x, h[0].y, acc[i][1]);
                    acc[i][1] = fmaf(w[i].y, h[1].y, acc[i][1]);
                    acc[i][1] = fmaf(w[i].z, h[2].y, acc[i][1]);
                    acc[i][1] = fmaf(w[i].w, h[3].y, acc[i][1]);
                    acc[i][2] = fmaf(w[i].x, h[0].z, acc[i][2]);
                    acc[i][2] = fmaf(w[i].y, h[1].z, acc[i][2]);
                    acc[i][2] = fmaf(w[i].z, h[2].z, acc[i][2]);
                    acc[i][2] = fmaf(w[i].w, h[3].z, acc[i][2]);
                    acc[i][3] = fmaf(w[i].x, h[0].w, acc[i][3]);
                    acc[i][3] = fmaf(w[i].y, h[1].w, acc[i][3]);
                    acc[i][3] = fmaf(w[i].z, h[2].w, acc[i][3]);
                    acc[i][3] = fmaf(w[i].w, h[3].w, acc[i][3]);
                }
            }
        }
        __syncthreads();
        if (g < 40) {
#pragma unroll
            for (int i = 0; i < 4; i++)
#pragma unroll
                for (int j = 0; j < 4; j++)
                    h0s[(ty * 4 + i) * H0S + g * 4 + j] = acc[i][j];
        }
        __syncthreads();
    }

    for (int e = tid; e < 512; e += 256) {
        int o = e >> 3, p = e & 7;
        float ss = s1s[o], oo = o1s[o];
        float m = -FINF;
#pragma unroll
        for (int kk = 0; kk < KNN; kk++) {
            float v = lrelu(fmaf(h0s[o * H0S + p * 20 + kk], ss, oo));
            m = fmaxf(m, v);
        }
        g_xc[((long)(b * 192 + outrow + o)) * NPTS + n0 + p] = m;
    }
}

// ---------------- small reductions ----------------
__global__ void k_gred(int width) {
    int e = blockIdx.x * 256 + threadIdx.x;
    if (e >= BATCH * 1024) return;
    const float* p = g_gpart + (long)e * width;
    float m = -FINF;
    for (int t = 0; t < width; t++) m = fmaxf(m, p[t]);
    g_g[e] = m;
}

__global__ void k_gterm(const float* __restrict__ wf1) {
    int e = blockIdx.x * 256 + threadIdx.x;
    if (e >= BATCH * 512) return;
    int b = e / 512, mo = e - b * 512;
    const float* w = wf1 + (long)mo * 1216 + 192;
    const float* gg = g_g + b * 1024;
    float acc = 0.f;
    for (int c = 0; c < 1024; c++) acc = fmaf(w[c], gg[c], acc);
    g_gterm[e] = acc;
}

// ---------------- host orchestration ----------------
#define EDGE2_SMEM ((4096 + 64 * H0S + 512 + 4 * 64) * 4 + 160 * 4)
#define SIM_TILES (32 * 33 / 2)

extern "C" void kernel_launch(void* const* d_in, const int* in_sizes, int n_in,
                              void* d_out, int out_size) {
    const float* x    = (const float*)d_in[0];
    const float* w1_0 = (const float*)d_in[1];
    const float* s1_0 = (const float*)d_in[2];
    const float* o1_0 = (const float*)d_in[3];
    const float* w1_1 = (const float*)d_in[4];
    const float* s1_1 = (const float*)d_in[5];
    const float* o1_1 = (const float*)d_in[6];
    const float* w2_0 = (const float*)d_in[7];
    const float* s2_0 = (const float*)d_in[8];
    const float* o2_0 = (const float*)d_in[9];
    const float* w2_1 = (const float*)d_in[10];
    const float* s2_1 = (const float*)d_in[11];
    const float* o2_1 = (const float*)d_in[12];
    const float* w3_0 = (const float*)d_in[13];
    const float* s3_0 = (const float*)d_in[14];
    const float* o3_0 = (const float*)d_in[15];
    const float* w3_1 = (const float*)d_in[16];
    const float* s3_1 = (const float*)d_in[17];
    const float* o3_1 = (const float*)d_in[18];
    const float* w4   = (const float*)d_in[19];
    const float* b4   = (const float*)d_in[20];
    const float* wf1  = (const float*)d_in[21];
    const float* sf1  = (const float*)d_in[22];
    const float* of1  = (const float*)d_in[23];
    const float* wf2  = (const float*)d_in[24];
    const float* sf2  = (const float*)d_in[25];
    const float* of2  = (const float*)d_in[26];
    const float* wf3  = (const float*)d_in[27];
    float* out = (float*)d_out;
    (void)in_sizes; (void)n_in; (void)out_size;

    float *p_xc, *p_xn, *p_uv, *p_w2, *p_gterm, *p_h1, *p_h2, *p_gpart, *p_dmat;
    cudaGetSymbolAddress((void**)&p_dmat,  g_dmat);
    cudaGetSymbolAddress((void**)&p_xc,    g_xc);
    cudaGetSymbolAddress((void**)&p_xn,    g_xn);
    cudaGetSymbolAddress((void**)&p_uv,    g_uv);
    cudaGetSymbolAddress((void**)&p_w2,    g_w2);
    cudaGetSymbolAddress((void**)&p_gpart, g_gpart);
    cudaGetSymbolAddress((void**)&p_gterm, g_gterm);
    cudaGetSymbolAddress((void**)&p_h1,    g_h1);
    cudaGetSymbolAddress((void**)&p_h2,    g_h2);

    cudaFuncSetAttribute(k_edge2, cudaFuncAttributeMaxDynamicSharedMemorySize, EDGE2_SMEM);

    dim3 knnG(NPTS / 8, BATCH);
    dim3 edgeG(NPTS / 8, BATCH);
    dim3 uvtG(4, 128, BATCH);
    dim3 simG(SIM_TILES, 1, BATCH);

    // ---- block 1: knn_euclid(x) + edge_conv1 -> xc[0:64) ----
    k_knn_euclid<<<knnG, 256>>>(x);
    k_w2prep<<<3, 256>>>(w1_0, 6);
    k_gemm<<<dim3(64, 2, BATCH), 256>>>(p_w2, 0, 6, 1, 0, x, (long)6 * NPTS,
                                        p_uv, (long)128 * NPTS, 128, 6,
                                        nullptr, nullptr, nullptr, 0, 0);
    k_uvt<<<uvtG, 256>>>();
    k_edge2<<<edgeG, 256, EDGE2_SMEM>>>(w1_1, s1_0, o1_0, s1_1, o1_1, 0);

    // ---- block 2: knn_cosine(x1) sym-GEMM (direct transposed write) ----
    k_normalize<<<dim3(16, BATCH), 256>>>(0);
    k_gemm_big<<<simG, 256>>>(p_xn, (long)64 * NPTS, 1, NPTS, 1,
                              p_xn, (long)64 * NPTS,
                              p_dmat, (long)NPTS * NPTS, NPTS, 64,
                              nullptr, nullptr, nullptr, 0, 1, nullptr, 1);
    k_topk_dmat<<<knnG, 256>>>();
    k_w2prep<<<32, 256>>>(w2_0, 64);
    k_gemm_big<<<dim3(32, 1, BATCH), 256>>>(p_w2, 0, 64, 0, 0, p_xc, (long)192 * NPTS,
                                            p_uv, (long)128 * NPTS, 128, 64,
                                            nullptr, nullptr, nullptr, 0, 0, nullptr, 0);
    k_uvt<<<uvtG, 256>>>();
    k_edge2<<<edgeG, 256, EDGE2_SMEM>>>(w2_1, s2_0, o2_0, s2_1, o2_1, 64);

    // ---- block 3: knn_cosine(x2) sym-GEMM (direct transposed write) ----
    k_normalize<<<dim3(16, BATCH), 256>>>(64);
    k_gemm_big<<<simG, 256>>>(p_xn, (long)64 * NPTS, 1, NPTS, 1,
                              p_xn, (long)64 * NPTS,
                              p_dmat, (long)NPTS * NPTS, NPTS, 64,
                              nullptr, nullptr, nullptr, 0, 1, nullptr, 1);
    k_topk_dmat<<<knnG, 256>>>();
    k_w2prep<<<32, 256>>>(w3_0, 64);
    k_gemm_big<<<dim3(32, 1, BATCH), 256>>>(p_w2, 0, 64, 0, 0, p_xc + (long)64 * NPTS, (long)192 * NPTS,
                                            p_uv, (long)128 * NPTS, 128, 64,
                                            nullptr, nullptr, nullptr, 0, 0, nullptr, 0);
    k_uvt<<<uvtG, 256>>>();
    k_edge2<<<edgeG, 256, EDGE2_SMEM>>>(w3_1, s3_0, o3_0, s3_1, o3_1, 128);

    // ---- head: w4 + fused global max-pool, gterm, wf1 -> wf2 -> wf3 ----
    k_gemm_big<<<dim3(32, 8, BATCH), 256>>>(w4, 0, 192, 0, 0, p_xc, (long)192 * NPTS,
                                            nullptr, 0, 1024, 192,
                                            nullptr, nullptr, b4, 1, 0, p_gpart, 0);
    k_gred<<<16, 256>>>(32);
    k_gterm<<<8, 256>>>(wf1);
    k_gemm_big<<<dim3(32, 4, BATCH), 256>>>(wf1, 0, 1216, 0, 0, p_xc, (long)192 * NPTS,
                                            p_h1, (long)512 * NPTS, 512, 192,
                                            p_gterm, sf1, of1, 1, 0, nullptr, 0);
    k_gemm_big<<<dim3(32, 2, BATCH), 256>>>(wf2, 0, 512, 0, 0, p_h1, (long)512 * NPTS,
                                            p_h2, (long)256 * NPTS, 256, 512,
                                            nullptr, sf2, of2, 1, 0, nullptr, 0);
    k_gemm<<<dim3(64, 1, BATCH), 256>>>(wf3, 0, 256, 1, 0, p_h2, (long)256 * NPTS,
                                        out, (long)13 * NPTS, 13, 256,
                                        nullptr, nullptr, nullptr, 0, 0);
}